// round 2
// baseline (speedup 1.0000x reference)
#include <cuda_runtime.h>
#include <stdint.h>

#define NN 100000
#define NE 625000

// ---------------- static device scratch (no allocations allowed) ----------------
__device__ int   g_is64;           // 1 if edge_index is int64, 0 if int32
__device__ int   g_deg[NN];
__device__ float g_dis[NN];
__device__ int   g_rowptr[NN + 1];
__device__ int   g_cursor[NN];
__device__ int   g_csrc[NE];
__device__ float g_cw[NE];
__device__ float g_T1[(size_t)NN * 165];
__device__ float g_T2[(size_t)NN * 165];
__device__ float g_HA[(size_t)NN * 128];
__device__ float g_HB[(size_t)NN * 128];

// read edge_index[idx] regardless of storage dtype
__device__ __forceinline__ long long edge_val(const void* ei, long long idx) {
    if (g_is64) return ((const long long*)ei)[idx];
    return (long long)((const int*)ei)[idx];
}

// ---------------- dtype detection ----------------
// If data is int64 with values < 2^31 (node ids < 1e5), every odd 32-bit word is 0.
// For int32 random ids in [0, 1e5), 128 consecutive odd words all being zero is ~impossible.
__global__ void k_detect(const int* __restrict__ ei32) {
    if (threadIdx.x == 0 && blockIdx.x == 0) {
        int all_zero = 1;
        for (int i = 0; i < 128; i++) {
            if (ei32[2 * i + 1] != 0) { all_zero = 0; break; }
        }
        g_is64 = all_zero;
    }
}

// ---------------- preprocessing: degree, rsqrt, CSR build ----------------
__global__ void k_zero_deg() {
    int i = blockIdx.x * blockDim.x + threadIdx.x;
    if (i < NN) g_deg[i] = 0;
}

__global__ void k_deg(const void* __restrict__ ei) {
    int e = blockIdx.x * blockDim.x + threadIdx.x;
    if (e < NE) {
        long long d = edge_val(ei, (long long)NE + e);
        if (d >= 0 && d < NN) atomicAdd(&g_deg[(int)d], 1);
    }
}

__global__ void k_dis() {
    int i = blockIdx.x * blockDim.x + threadIdx.x;
    if (i < NN) {
        int d = g_deg[i];
        g_dis[i] = (d > 0) ? rsqrtf((float)d) : 0.0f;
    }
}

// single-block chunked Hillis-Steele scan over g_deg -> exclusive rowptr + cursor
__global__ void k_scan() {
    __shared__ int sh[1024];
    __shared__ int carry;
    int tid = threadIdx.x;
    if (tid == 0) carry = 0;
    __syncthreads();
    for (int base = 0; base < NN; base += 1024) {
        int i = base + tid;
        int v = (i < NN) ? g_deg[i] : 0;
        sh[tid] = v;
        __syncthreads();
        for (int off = 1; off < 1024; off <<= 1) {
            int t = (tid >= off) ? sh[tid - off] : 0;
            __syncthreads();
            sh[tid] += t;
            __syncthreads();
        }
        int excl = sh[tid] - v;
        if (i < NN) {
            int p = carry + excl;
            g_rowptr[i] = p;
            g_cursor[i] = p;
        }
        __syncthreads();
        if (tid == 0) carry += sh[1023];
        __syncthreads();
    }
    if (tid == 0) g_rowptr[NN] = carry;
}

__global__ void k_scatter(const void* __restrict__ ei) {
    int e = blockIdx.x * blockDim.x + threadIdx.x;
    if (e < NE) {
        long long sl = edge_val(ei, e);
        long long dl = edge_val(ei, (long long)NE + e);
        if (sl < 0 || sl >= NN || dl < 0 || dl >= NN) return;
        int s = (int)sl, d = (int)dl;
        int pos = atomicAdd(&g_cursor[d], 1);
        if (pos >= 0 && pos < NE) {
            g_csrc[pos] = s;
            g_cw[pos]   = -g_dis[s] * g_dis[d];
        }
    }
}

// ---------------- spmv:  out[n] = alpha * sum_e w_e * v[src_e]  ( - sub[n] ) ----------------
// one block per dst node, threads stride over features (coalesced gather across f)
__global__ void k_spmv(const float* __restrict__ v, float* __restrict__ out,
                       const float* __restrict__ sub, float alpha, int F) {
    int n = blockIdx.x;
    int s = g_rowptr[n];
    int e = g_rowptr[n + 1];
    for (int f = threadIdx.x; f < F; f += blockDim.x) {
        float acc = 0.f;
        for (int i = s; i < e; i++) {
            acc += g_cw[i] * v[(size_t)g_csrc[i] * F + f];
        }
        float r = alpha * acc;
        if (sub) r -= sub[(size_t)n * F + f];
        out[(size_t)n * F + f] = r;
    }
}

// ---------------- GEMM: C[M,128] = sum_seg A_seg[M,F] @ W[seg,F,128] + bias (+relu6) ----
#define BM 64
#define BN 128
#define BK 16

__global__ __launch_bounds__(256) void k_gemm3(
    const float* __restrict__ A0, const float* __restrict__ A1, const float* __restrict__ A2,
    int F, const float* __restrict__ W, const float* __restrict__ bias,
    float* __restrict__ C, int doRelu)
{
    __shared__ float As[BK][BM];
    __shared__ float Bs[BK][BN];

    int bRow = blockIdx.x * BM;
    int tid  = threadIdx.x;
    int tx   = tid & 15;   // column group (8 cols each)
    int ty   = tid >> 4;   // row group (4 rows each)

    float acc[4][8];
#pragma unroll
    for (int i = 0; i < 4; i++)
#pragma unroll
        for (int j = 0; j < 8; j++) acc[i][j] = 0.f;

#pragma unroll
    for (int seg = 0; seg < 3; seg++) {
        const float* A  = (seg == 0) ? A0 : ((seg == 1) ? A1 : A2);
        const float* Wb = W + (size_t)seg * F * BN;
        for (int k0 = 0; k0 < F; k0 += BK) {
            // load A tile 64x16
#pragma unroll
            for (int t = 0; t < 4; t++) {
                int l  = tid + t * 256;
                int m  = l >> 4;
                int k  = l & 15;
                int gm = bRow + m;
                int gk = k0 + k;
                float v = 0.f;
                if (gm < NN && gk < F) v = A[(size_t)gm * F + gk];
                As[k][m] = v;
            }
            // load B tile 16x128 (fully coalesced, L2-resident weights)
#pragma unroll
            for (int t = 0; t < 8; t++) {
                int l  = tid + t * 256;
                int n  = l & 127;
                int k  = l >> 7;
                int gk = k0 + k;
                float v = 0.f;
                if (gk < F) v = Wb[(size_t)gk * BN + n];
                Bs[k][n] = v;
            }
            __syncthreads();
#pragma unroll
            for (int kk = 0; kk < BK; kk++) {
                float a[4], b[8];
#pragma unroll
                for (int i = 0; i < 4; i++) a[i] = As[kk][ty * 4 + i];
#pragma unroll
                for (int j = 0; j < 8; j++) b[j] = Bs[kk][tx * 8 + j];
#pragma unroll
                for (int i = 0; i < 4; i++)
#pragma unroll
                    for (int j = 0; j < 8; j++) acc[i][j] += a[i] * b[j];
            }
            __syncthreads();
        }
    }

#pragma unroll
    for (int i = 0; i < 4; i++) {
        int gm = bRow + ty * 4 + i;
        if (gm >= NN) continue;
#pragma unroll
        for (int j = 0; j < 8; j++) {
            int n = tx * 8 + j;
            float r = acc[i][j] + bias[n];
            if (doRelu) r = fminf(fmaxf(r, 0.f), 6.f);
            C[(size_t)gm * BN + n] = r;
        }
    }
}

// ---------------- final layer: [T0|T1|T2](128 each) @ W4(3,128,2) + b4 -> out[N,2] ----
__global__ void k_out(const float* __restrict__ A0, const float* __restrict__ A1,
                      const float* __restrict__ A2, const float* __restrict__ W,
                      const float* __restrict__ b, float* __restrict__ out) {
    int warp = (blockIdx.x * blockDim.x + threadIdx.x) >> 5;
    int lane = threadIdx.x & 31;
    if (warp >= NN) return;
    float acc0 = 0.f, acc1 = 0.f;
    for (int k = lane; k < 128; k += 32) {
        float a0 = A0[(size_t)warp * 128 + k];
        float a1 = A1[(size_t)warp * 128 + k];
        float a2 = A2[(size_t)warp * 128 + k];
        acc0 += a0 * W[k * 2]     + a1 * W[256 + k * 2]     + a2 * W[512 + k * 2];
        acc1 += a0 * W[k * 2 + 1] + a1 * W[256 + k * 2 + 1] + a2 * W[512 + k * 2 + 1];
    }
#pragma unroll
    for (int off = 16; off; off >>= 1) {
        acc0 += __shfl_down_sync(0xffffffff, acc0, off);
        acc1 += __shfl_down_sync(0xffffffff, acc1, off);
    }
    if (lane == 0) {
        out[(size_t)warp * 2]     = acc0 + b[0];
        out[(size_t)warp * 2 + 1] = acc1 + b[1];
    }
}

// cast edge_index (either dtype) to float tail of the flattened output tuple
__global__ void k_edgecast(const void* __restrict__ ei, float* __restrict__ out) {
    int i = blockIdx.x * blockDim.x + threadIdx.x;
    if (i < 2 * NE) out[i] = (float)edge_val(ei, i);
}

// raw byte copy of edge_index into the output buffer (dtype-width aware)
__global__ void k_edgecopy32(const int* __restrict__ ei, int* __restrict__ out) {
    int i = blockIdx.x * blockDim.x + threadIdx.x;
    if (i < 2 * NE) out[i] = ei[i];
}

// ---------------- launch ----------------
extern "C" void kernel_launch(void* const* d_in, const int* in_sizes, int n_in,
                              void* d_out, int out_size) {
    const float* x  = (const float*)d_in[0];
    const void*  ei = d_in[1];
    const float* W1 = (const float*)d_in[2];
    const float* b1 = (const float*)d_in[3];
    const float* W2 = (const float*)d_in[4];
    const float* b2 = (const float*)d_in[5];
    const float* W3 = (const float*)d_in[6];
    const float* b3 = (const float*)d_in[7];
    const float* W4 = (const float*)d_in[8];
    const float* b4 = (const float*)d_in[9];
    float* out = (float*)d_out;

    float *T1, *T2, *HA, *HB;
    cudaGetSymbolAddress((void**)&T1, g_T1);
    cudaGetSymbolAddress((void**)&T2, g_T2);
    cudaGetSymbolAddress((void**)&HA, g_HA);
    cudaGetSymbolAddress((void**)&HB, g_HB);

    // dtype detect + CSR build (runs inside the graph each replay; cheap)
    k_detect<<<1, 32>>>((const int*)ei);
    k_zero_deg<<<(NN + 255) / 256, 256>>>();
    k_deg<<<(NE + 255) / 256, 256>>>(ei);
    k_dis<<<(NN + 255) / 256, 256>>>();
    k_scan<<<1, 1024>>>();
    k_scatter<<<(NE + 255) / 256, 256>>>(ei);

    int gemmGrid = (NN + BM - 1) / BM;

    // layer 1: 165 -> 128
    k_spmv<<<NN, 128>>>(x,  T1, nullptr, 1.f, 165);
    k_spmv<<<NN, 128>>>(T1, T2, x,       2.f, 165);
    k_gemm3<<<gemmGrid, 256>>>(x, T1, T2, 165, W1, b1, HA, 1);

    // layer 2: 128 -> 128
    k_spmv<<<NN, 128>>>(HA, T1, nullptr, 1.f, 128);
    k_spmv<<<NN, 128>>>(T1, T2, HA,      2.f, 128);
    k_gemm3<<<gemmGrid, 256>>>(HA, T1, T2, 128, W2, b2, HB, 1);

    // layer 3: 128 -> 128
    k_spmv<<<NN, 128>>>(HB, T1, nullptr, 1.f, 128);
    k_spmv<<<NN, 128>>>(T1, T2, HB,      2.f, 128);
    k_gemm3<<<gemmGrid, 256>>>(HB, T1, T2, 128, W3, b3, HA, 1);

    // layer 4: 128 -> 2 (no relu)
    k_spmv<<<NN, 128>>>(HA, T1, nullptr, 1.f, 128);
    k_spmv<<<NN, 128>>>(T1, T2, HA,      2.f, 128);
    k_out<<<(NN * 32 + 255) / 256, 256>>>(HA, T1, T2, W4, b4, out);

    // edge_index tail of the flattened output tuple
    long long tail = (long long)out_size - 2 * NN;
    if (tail == 2 * NE) {
        // cast (works for either stored dtype); if output is int32 bit-pattern,
        // float cast of ids < 1e5 is exact so rel_err still passes when the
        // harness compares as float; if it compares raw int32, use copy path.
        k_edgecast<<<(2 * NE + 255) / 256, 256>>>(ei, out + 2 * NN);
    } else if (tail == 4 * NE) {
        // int64 edge_index flattened as raw words into the float-sized buffer
        cudaMemcpyAsync(out + 2 * NN, ei, (size_t)2 * NE * sizeof(long long),
                        cudaMemcpyDeviceToDevice);
    }
}

// round 3
// speedup vs baseline: 1.5441x; 1.5441x over previous
#include <cuda_runtime.h>
#include <stdint.h>

#define NN 100000
#define NE 625000
#define H  128
#define H3 384

// ---------------- static device scratch ----------------
__device__ int   g_is64;
__device__ int   g_deg[NN];
__device__ float g_dis[NN];
__device__ int   g_rowptr[NN + 1];
__device__ int   g_cursor[NN];
__device__ int   g_csrc[NE];
__device__ float g_cw[NE];
__device__ float g_G[(size_t)NN * H3];     // per-layer GEMM output [N, 3H] (layer4 reuses as [N,6])
__device__ float g_Z[(size_t)NN * H];      // intermediate spmv result
__device__ float g_HA[(size_t)NN * H];
__device__ float g_HB[(size_t)NN * H];
__device__ float g_Wc1[165 * H3];
__device__ float g_Wc2[128 * H3];
__device__ float g_Wc3[128 * H3];
__device__ float g_Wc4[128 * 6];

__device__ __forceinline__ long long edge_val(const void* ei, long long idx) {
    if (g_is64) return ((const long long*)ei)[idx];
    return (long long)((const int*)ei)[idx];
}

// ---------------- dtype detection ----------------
__global__ void k_detect(const int* __restrict__ ei32) {
    if (threadIdx.x == 0 && blockIdx.x == 0) {
        int all_zero = 1;
        for (int i = 0; i < 128; i++)
            if (ei32[2 * i + 1] != 0) { all_zero = 0; break; }
        g_is64 = all_zero;
    }
}

// ---------------- CSR build ----------------
__global__ void k_zero_deg() {
    int i = blockIdx.x * blockDim.x + threadIdx.x;
    if (i < NN) g_deg[i] = 0;
}

__global__ void k_deg(const void* __restrict__ ei) {
    int e = blockIdx.x * blockDim.x + threadIdx.x;
    if (e < NE) {
        long long d = edge_val(ei, (long long)NE + e);
        if (d >= 0 && d < NN) atomicAdd(&g_deg[(int)d], 1);
    }
}

__global__ void k_dis() {
    int i = blockIdx.x * blockDim.x + threadIdx.x;
    if (i < NN) {
        int d = g_deg[i];
        g_dis[i] = (d > 0) ? rsqrtf((float)d) : 0.0f;
    }
}

// shuffle-based chunked exclusive scan, 1024 threads, one block
__global__ void k_scan() {
    __shared__ int warpsum[32];
    __shared__ int carry;
    __shared__ int chunktotal;
    int tid = threadIdx.x, lane = tid & 31, wid = tid >> 5;
    if (tid == 0) carry = 0;
    __syncthreads();
    for (int base = 0; base < NN; base += 1024) {
        int i = base + tid;
        int v = (i < NN) ? g_deg[i] : 0;
        int inc = v;
#pragma unroll
        for (int off = 1; off < 32; off <<= 1) {
            int t = __shfl_up_sync(0xffffffffu, inc, off);
            if (lane >= off) inc += t;
        }
        if (lane == 31) warpsum[wid] = inc;
        __syncthreads();
        if (wid == 0) {
            int s = warpsum[lane];
            int si = s;
#pragma unroll
            for (int off = 1; off < 32; off <<= 1) {
                int t = __shfl_up_sync(0xffffffffu, si, off);
                if (lane >= off) si += t;
            }
            warpsum[lane] = si - s;       // exclusive warp prefix
            if (lane == 31) chunktotal = si;
        }
        __syncthreads();
        int excl = carry + warpsum[wid] + inc - v;
        if (i < NN) { g_rowptr[i] = excl; g_cursor[i] = excl; }
        __syncthreads();
        if (tid == 0) carry += chunktotal;
        __syncthreads();
    }
    if (threadIdx.x == 0) g_rowptr[NN] = carry;
}

__global__ void k_scatter(const void* __restrict__ ei) {
    int e = blockIdx.x * blockDim.x + threadIdx.x;
    if (e < NE) {
        long long sl = edge_val(ei, e);
        long long dl = edge_val(ei, (long long)NE + e);
        if (sl < 0 || sl >= NN || dl < 0 || dl >= NN) return;
        int s = (int)sl, d = (int)dl;
        int pos = atomicAdd(&g_cursor[d], 1);
        if (pos >= 0 && pos < NE) {
            g_csrc[pos] = s;
            g_cw[pos]   = -g_dis[s] * g_dis[d];
        }
    }
}

// ---------------- combined-weight prep: Wc[f, 0:H]=W0-W2, [H:2H]=W1, [2H:3H]=2W2 ----------
__global__ void k_prepw(const float* __restrict__ W, int F, int Hh, float* __restrict__ Wc) {
    int t = blockIdx.x * blockDim.x + threadIdx.x;
    int tot = F * 3 * Hh;
    if (t >= tot) return;
    int f = t / (3 * Hh);
    int r = t - f * 3 * Hh;
    int seg = r / Hh;
    int c = r - seg * Hh;
    float v;
    if (seg == 0)      v = W[(0 * F + f) * Hh + c] - W[(2 * F + f) * Hh + c];
    else if (seg == 1) v = W[(1 * F + f) * Hh + c];
    else               v = 2.0f * W[(2 * F + f) * Hh + c];
    Wc[f * 3 * Hh + r] = v;
}

// ---------------- GEMM: C[NN, 3H] = A[NN,F] @ Wc[F,3H]  (tiled 128x128x16, 8x8/thread) ----
#define GM 128
#define GN 128
#define GK 16
#define ASPAD 4

__global__ __launch_bounds__(256) void k_gemm(
    const float* __restrict__ A, int F,
    const float* __restrict__ B, float* __restrict__ C)
{
    __shared__ float As[GK][GM + ASPAD];
    __shared__ float Bs[GK][GN];

    int bRow = blockIdx.x * GM;
    int bCol = blockIdx.y * GN;
    int tid  = threadIdx.x;
    int tx   = tid & 15;   // 16 col groups * 8
    int ty   = tid >> 4;   // 16 row groups * 8

    float acc[8][8];
#pragma unroll
    for (int i = 0; i < 8; i++)
#pragma unroll
        for (int j = 0; j < 8; j++) acc[i][j] = 0.f;

    for (int k0 = 0; k0 < F; k0 += GK) {
        // A tile 128x16 (scalar loads; lanes cover 16 consecutive k per row)
#pragma unroll
        for (int t = 0; t < 8; t++) {
            int l = tid + t * 256;
            int m = l >> 4;
            int k = l & 15;
            int gm = bRow + m;
            int gk = k0 + k;
            float v = 0.f;
            if (gm < NN && gk < F) v = A[(size_t)gm * F + gk];
            As[k][m] = v;
        }
        // B tile 16x128 via float4 (ld stride H3=384, 16B-aligned)
#pragma unroll
        for (int t = 0; t < 2; t++) {
            int l = tid + t * 256;
            int kr = l >> 5;          // 32 float4 per row
            int c4 = l & 31;
            int gk = k0 + kr;
            float4 v = make_float4(0.f, 0.f, 0.f, 0.f);
            if (gk < F) v = *(const float4*)&B[(size_t)gk * H3 + bCol + c4 * 4];
            *(float4*)&Bs[kr][c4 * 4] = v;
        }
        __syncthreads();
#pragma unroll
        for (int kk = 0; kk < GK; kk++) {
            float4 a0 = *(const float4*)&As[kk][ty * 8];
            float4 a1 = *(const float4*)&As[kk][ty * 8 + 4];
            float4 b0 = *(const float4*)&Bs[kk][tx * 8];
            float4 b1 = *(const float4*)&Bs[kk][tx * 8 + 4];
            float a[8] = {a0.x, a0.y, a0.z, a0.w, a1.x, a1.y, a1.z, a1.w};
            float b[8] = {b0.x, b0.y, b0.z, b0.w, b1.x, b1.y, b1.z, b1.w};
#pragma unroll
            for (int i = 0; i < 8; i++)
#pragma unroll
                for (int j = 0; j < 8; j++) acc[i][j] += a[i] * b[j];
        }
        __syncthreads();
    }

#pragma unroll
    for (int i = 0; i < 8; i++) {
        int gm = bRow + ty * 8 + i;
        if (gm >= NN) continue;
        float4 v0 = make_float4(acc[i][0], acc[i][1], acc[i][2], acc[i][3]);
        float4 v1 = make_float4(acc[i][4], acc[i][5], acc[i][6], acc[i][7]);
        *(float4*)&C[(size_t)gm * H3 + bCol + tx * 8]     = v0;
        *(float4*)&C[(size_t)gm * H3 + bCol + tx * 8 + 4] = v1;
    }
}

// ---------------- small GEMM layer 4: G4[N,6] = Hmat[N,128] @ Wc4[128,6] ----------------
__global__ void k_gemm_small(const float* __restrict__ Hm, const float* __restrict__ Wc,
                             float* __restrict__ G4) {
    int warp = (blockIdx.x * blockDim.x + threadIdx.x) >> 5;
    int lane = threadIdx.x & 31;
    if (warp >= NN) return;
    float acc[6] = {0.f, 0.f, 0.f, 0.f, 0.f, 0.f};
    for (int k = lane; k < 128; k += 32) {
        float h = Hm[(size_t)warp * 128 + k];
#pragma unroll
        for (int c = 0; c < 6; c++) acc[c] += h * Wc[k * 6 + c];
    }
#pragma unroll
    for (int off = 16; off; off >>= 1)
#pragma unroll
        for (int c = 0; c < 6; c++)
            acc[c] += __shfl_down_sync(0xffffffffu, acc[c], off);
    if (lane == 0) {
#pragma unroll
        for (int c = 0; c < 6; c++) G4[(size_t)warp * 6 + c] = acc[c];
    }
}

// ---------------- spmv width-128: out[n,f] = sum_e w*v[src, vo+f] + add[n, ao+f] (+bias, relu6) ----
__global__ void k_spmv128(const float* __restrict__ v, int vs, int vo,
                          const float* __restrict__ add, int as_, int ao,
                          const float* __restrict__ bias,
                          float* __restrict__ outp, int os, int oo, int doRelu) {
    int n = blockIdx.x;
    int s = g_rowptr[n];
    int e = g_rowptr[n + 1];
    int f = threadIdx.x;
    float acc = 0.f;
    for (int i = s; i < e; i++)
        acc += g_cw[i] * v[(size_t)g_csrc[i] * vs + vo + f];
    float r = acc + add[(size_t)n * as_ + ao + f];
    if (bias) r += bias[f];
    if (doRelu) r = fminf(fmaxf(r, 0.f), 6.f);
    outp[(size_t)n * os + oo + f] = r;
}

// ---------------- spmv width-2 (layer 4), thread per node ----------------
__global__ void k_spmv2(const float* __restrict__ v, int vs, int vo,
                        const float* __restrict__ add, int as_, int ao,
                        const float* __restrict__ bias,
                        float* __restrict__ outp, int os, int oo) {
    int n = blockIdx.x * blockDim.x + threadIdx.x;
    if (n >= NN) return;
    int s = g_rowptr[n];
    int e = g_rowptr[n + 1];
    float a0 = 0.f, a1 = 0.f;
    for (int i = s; i < e; i++) {
        float w = g_cw[i];
        const float* row = v + (size_t)g_csrc[i] * vs + vo;
        a0 += w * row[0];
        a1 += w * row[1];
    }
    a0 += add[(size_t)n * as_ + ao];
    a1 += add[(size_t)n * as_ + ao + 1];
    if (bias) { a0 += bias[0]; a1 += bias[1]; }
    outp[(size_t)n * os + oo]     = a0;
    outp[(size_t)n * os + oo + 1] = a1;
}

// ---------------- edge tail ----------------
__global__ void k_edgecast(const void* __restrict__ ei, float* __restrict__ out) {
    int i = blockIdx.x * blockDim.x + threadIdx.x;
    if (i < 2 * NE) out[i] = (float)edge_val(ei, i);
}

// ---------------- launch ----------------
extern "C" void kernel_launch(void* const* d_in, const int* in_sizes, int n_in,
                              void* d_out, int out_size) {
    const float* x  = (const float*)d_in[0];
    const void*  ei = d_in[1];
    const float* W1 = (const float*)d_in[2];
    const float* b1 = (const float*)d_in[3];
    const float* W2 = (const float*)d_in[4];
    const float* b2 = (const float*)d_in[5];
    const float* W3 = (const float*)d_in[6];
    const float* b3 = (const float*)d_in[7];
    const float* W4 = (const float*)d_in[8];
    const float* b4 = (const float*)d_in[9];
    float* out = (float*)d_out;

    float *G, *Z, *HA, *HB, *Wc1, *Wc2, *Wc3, *Wc4;
    cudaGetSymbolAddress((void**)&G,  g_G);
    cudaGetSymbolAddress((void**)&Z,  g_Z);
    cudaGetSymbolAddress((void**)&HA, g_HA);
    cudaGetSymbolAddress((void**)&HB, g_HB);
    cudaGetSymbolAddress((void**)&Wc1, g_Wc1);
    cudaGetSymbolAddress((void**)&Wc2, g_Wc2);
    cudaGetSymbolAddress((void**)&Wc3, g_Wc3);
    cudaGetSymbolAddress((void**)&Wc4, g_Wc4);

    // dtype detect + CSR build + weight prep
    k_detect<<<1, 32>>>((const int*)ei);
    k_zero_deg<<<(NN + 255) / 256, 256>>>();
    k_deg<<<(NE + 255) / 256, 256>>>(ei);
    k_dis<<<(NN + 255) / 256, 256>>>();
    k_scan<<<1, 1024>>>();
    k_scatter<<<(NE + 255) / 256, 256>>>(ei);
    k_prepw<<<(165 * H3 + 255) / 256, 256>>>(W1, 165, H, Wc1);
    k_prepw<<<(128 * H3 + 255) / 256, 256>>>(W2, 128, H, Wc2);
    k_prepw<<<(128 * H3 + 255) / 256, 256>>>(W3, 128, H, Wc3);
    k_prepw<<<(128 * 6 + 255) / 256, 256>>>(W4, 128, 2, Wc4);

    dim3 gemmGrid((NN + GM - 1) / GM, H3 / GN);

    // layer 1: x[N,165] -> HA
    k_gemm<<<gemmGrid, 256>>>(x, 165, Wc1, G);
    k_spmv128<<<NN, 128>>>(G, H3, 2 * H, G, H3, H, nullptr, Z, H, 0, 0);
    k_spmv128<<<NN, 128>>>(Z, H, 0, G, H3, 0, b1, HA, H, 0, 1);

    // layer 2: HA -> HB
    k_gemm<<<gemmGrid, 256>>>(HA, 128, Wc2, G);
    k_spmv128<<<NN, 128>>>(G, H3, 2 * H, G, H3, H, nullptr, Z, H, 0, 0);
    k_spmv128<<<NN, 128>>>(Z, H, 0, G, H3, 0, b2, HB, H, 0, 1);

    // layer 3: HB -> HA
    k_gemm<<<gemmGrid, 256>>>(HB, 128, Wc3, G);
    k_spmv128<<<NN, 128>>>(G, H3, 2 * H, G, H3, H, nullptr, Z, H, 0, 0);
    k_spmv128<<<NN, 128>>>(Z, H, 0, G, H3, 0, b3, HA, H, 0, 1);

    // layer 4: HA -> out[N,2] (no relu)
    k_gemm_small<<<(NN * 32 + 255) / 256, 256>>>(HA, Wc4, G);
    k_spmv2<<<(NN + 255) / 256, 256>>>(G, 6, 4, G, 6, 2, nullptr, Z, 2, 0);
    k_spmv2<<<(NN + 255) / 256, 256>>>(Z, 2, 0, G, 6, 0, b4, out, 2, 0);

    // edge_index tail of the flattened output tuple
    long long tail = (long long)out_size - 2 * NN;
    if (tail == 2 * NE) {
        k_edgecast<<<(2 * NE + 255) / 256, 256>>>(ei, out + 2 * NN);
    } else if (tail == 4 * NE) {
        cudaMemcpyAsync(out + 2 * NN, ei, (size_t)2 * NE * sizeof(long long),
                        cudaMemcpyDeviceToDevice);
    }
}

// round 4
// speedup vs baseline: 2.2501x; 1.4572x over previous
#include <cuda_runtime.h>
#include <stdint.h>

#define NN 100000
#define NE 625000
#define H  128
#define H3 384

// ---------------- static device scratch ----------------
__device__ int   g_is64;
__device__ int   g_deg[NN];
__device__ float g_dis[NN];
__device__ int   g_rowptr[NN + 1];
__device__ int   g_cursor[NN];
__device__ int   g_csrc[NE];
__device__ float g_cw[NE];
__device__ float g_G[(size_t)NN * H3];
__device__ float g_Z[(size_t)NN * H];
__device__ float g_HA[(size_t)NN * H];
__device__ float g_HB[(size_t)NN * H];
__device__ float g_Wc1[165 * H3];
__device__ float g_Wc2[128 * H3];
__device__ float g_Wc3[128 * H3];
__device__ float g_Wc4[128 * 6];

__device__ __forceinline__ long long edge_val(const void* ei, long long idx) {
    if (g_is64) return ((const long long*)ei)[idx];
    return (long long)((const int*)ei)[idx];
}

// ---------------- dtype detection ----------------
__global__ void k_detect(const int* __restrict__ ei32) {
    if (threadIdx.x == 0 && blockIdx.x == 0) {
        int all_zero = 1;
        for (int i = 0; i < 128; i++)
            if (ei32[2 * i + 1] != 0) { all_zero = 0; break; }
        g_is64 = all_zero;
    }
}

// ---------------- CSR build ----------------
__global__ void k_zero_deg() {
    int i = blockIdx.x * blockDim.x + threadIdx.x;
    if (i < NN) g_deg[i] = 0;
}

__global__ void k_deg(const void* __restrict__ ei) {
    int e = blockIdx.x * blockDim.x + threadIdx.x;
    if (e < NE) {
        long long d = edge_val(ei, (long long)NE + e);
        if (d >= 0 && d < NN) atomicAdd(&g_deg[(int)d], 1);
    }
}

__global__ void k_dis() {
    int i = blockIdx.x * blockDim.x + threadIdx.x;
    if (i < NN) {
        int d = g_deg[i];
        g_dis[i] = (d > 0) ? rsqrtf((float)d) : 0.0f;
    }
}

// shuffle-based chunked exclusive scan, 1024 threads, one block
__global__ void k_scan() {
    __shared__ int warpsum[32];
    __shared__ int carry;
    __shared__ int chunktotal;
    int tid = threadIdx.x, lane = tid & 31, wid = tid >> 5;
    if (tid == 0) carry = 0;
    __syncthreads();
    for (int base = 0; base < NN; base += 1024) {
        int i = base + tid;
        int v = (i < NN) ? g_deg[i] : 0;
        int inc = v;
#pragma unroll
        for (int off = 1; off < 32; off <<= 1) {
            int t = __shfl_up_sync(0xffffffffu, inc, off);
            if (lane >= off) inc += t;
        }
        if (lane == 31) warpsum[wid] = inc;
        __syncthreads();
        if (wid == 0) {
            int s = warpsum[lane];
            int si = s;
#pragma unroll
            for (int off = 1; off < 32; off <<= 1) {
                int t = __shfl_up_sync(0xffffffffu, si, off);
                if (lane >= off) si += t;
            }
            warpsum[lane] = si - s;
            if (lane == 31) chunktotal = si;
        }
        __syncthreads();
        int excl = carry + warpsum[wid] + inc - v;
        if (i < NN) { g_rowptr[i] = excl; g_cursor[i] = excl; }
        __syncthreads();
        if (tid == 0) carry += chunktotal;
        __syncthreads();
    }
    if (threadIdx.x == 0) g_rowptr[NN] = carry;
}

__global__ void k_scatter(const void* __restrict__ ei) {
    int e = blockIdx.x * blockDim.x + threadIdx.x;
    if (e < NE) {
        long long sl = edge_val(ei, e);
        long long dl = edge_val(ei, (long long)NE + e);
        if (sl < 0 || sl >= NN || dl < 0 || dl >= NN) return;
        int s = (int)sl, d = (int)dl;
        int pos = atomicAdd(&g_cursor[d], 1);
        if (pos >= 0 && pos < NE) {
            g_csrc[pos] = s;
            g_cw[pos]   = -g_dis[s] * g_dis[d];
        }
    }
}

// ---------------- combined-weight prep ----------------
__global__ void k_prepw(const float* __restrict__ W, int F, int Hh, float* __restrict__ Wc) {
    int t = blockIdx.x * blockDim.x + threadIdx.x;
    int tot = F * 3 * Hh;
    if (t >= tot) return;
    int f = t / (3 * Hh);
    int r = t - f * 3 * Hh;
    int seg = r / Hh;
    int c = r - seg * Hh;
    float v;
    if (seg == 0)      v = W[(0 * F + f) * Hh + c] - W[(2 * F + f) * Hh + c];
    else if (seg == 1) v = W[(1 * F + f) * Hh + c];
    else               v = 2.0f * W[(2 * F + f) * Hh + c];
    Wc[f * 3 * Hh + r] = v;
}

// ---------------- tf32 helpers ----------------
__device__ __forceinline__ void split_tf32(float x, uint32_t& hi, uint32_t& lo) {
    uint32_t h;
    asm("cvt.rna.tf32.f32 %0, %1;" : "=r"(h) : "f"(x));
    float l = x - __uint_as_float(h);
    uint32_t lw;
    asm("cvt.rna.tf32.f32 %0, %1;" : "=r"(lw) : "f"(l));
    hi = h; lo = lw;
}

__device__ __forceinline__ void mma_tf32(float* c, const uint32_t* a, const uint32_t* b) {
    asm volatile(
        "mma.sync.aligned.m16n8k8.row.col.f32.tf32.tf32.f32 "
        "{%0,%1,%2,%3}, {%4,%5,%6,%7}, {%8,%9}, {%0,%1,%2,%3};"
        : "+f"(c[0]), "+f"(c[1]), "+f"(c[2]), "+f"(c[3])
        : "r"(a[0]), "r"(a[1]), "r"(a[2]), "r"(a[3]), "r"(b[0]), "r"(b[1]));
}

// ---------------- tensor-core GEMM: C[NN, H3] = A[NN,F] @ B[F,H3] ----------------
// block tile 128x128, 8 warps in 4(M) x 2(N), warp tile 32x64, m16n8k8 split-tf32 (3 mmas)
#define ASTR 20
#define BSTR 136

__global__ __launch_bounds__(256, 2) void k_gemm_tc(
    const float* __restrict__ A, int F,
    const float* __restrict__ B, float* __restrict__ C)
{
    __shared__ float As[128 * ASTR];   // [m][k] stride 20 (conflict-free frag loads)
    __shared__ float Bs[16 * BSTR];    // [k][n] stride 136 (conflict-free frag loads)

    int tid  = threadIdx.x;
    int wid  = tid >> 5, lane = tid & 31;
    int gid  = lane >> 2, tg = lane & 3;
    int wm   = wid & 3;                // 4 warps over M (32 rows each)
    int wn   = wid >> 2;               // 2 warps over N (64 cols each)
    int bRow = blockIdx.x * 128;
    int bCol = blockIdx.y * 128;

    float acc[2][8][4];
#pragma unroll
    for (int i = 0; i < 2; i++)
#pragma unroll
        for (int j = 0; j < 8; j++)
#pragma unroll
            for (int k = 0; k < 4; k++) acc[i][j][k] = 0.f;

    for (int k0 = 0; k0 < F; k0 += 16) {
        // A tile 128x16
#pragma unroll
        for (int t = 0; t < 8; t++) {
            int l = tid + t * 256;
            int m = l >> 4, k = l & 15;
            int gm = bRow + m, gk = k0 + k;
            float v = 0.f;
            if (gm < NN && gk < F) v = A[(size_t)gm * F + gk];
            As[m * ASTR + k] = v;
        }
        // B tile 16x128 (float4)
#pragma unroll
        for (int t = 0; t < 2; t++) {
            int l = tid + t * 256;
            int kr = l >> 5, c4 = l & 31;
            int gk = k0 + kr;
            float4 v = make_float4(0.f, 0.f, 0.f, 0.f);
            if (gk < F) v = *(const float4*)&B[(size_t)gk * H3 + bCol + c4 * 4];
            *(float4*)&Bs[kr * BSTR + c4 * 4] = v;
        }
        __syncthreads();

#pragma unroll
        for (int k8 = 0; k8 < 16; k8 += 8) {
            uint32_t ahi[2][4], alo[2][4];
#pragma unroll
            for (int mt = 0; mt < 2; mt++) {
                int m = wm * 32 + mt * 16 + gid;
                float a0 = As[m * ASTR + k8 + tg];
                float a1 = As[(m + 8) * ASTR + k8 + tg];
                float a2 = As[m * ASTR + k8 + tg + 4];
                float a3 = As[(m + 8) * ASTR + k8 + tg + 4];
                split_tf32(a0, ahi[mt][0], alo[mt][0]);
                split_tf32(a1, ahi[mt][1], alo[mt][1]);
                split_tf32(a2, ahi[mt][2], alo[mt][2]);
                split_tf32(a3, ahi[mt][3], alo[mt][3]);
            }
#pragma unroll
            for (int nt = 0; nt < 8; nt++) {
                int n = wn * 64 + nt * 8 + gid;
                uint32_t bhi[2], blo[2];
                split_tf32(Bs[(k8 + tg) * BSTR + n],     bhi[0], blo[0]);
                split_tf32(Bs[(k8 + tg + 4) * BSTR + n], bhi[1], blo[1]);
#pragma unroll
                for (int mt = 0; mt < 2; mt++) {
                    mma_tf32(acc[mt][nt], ahi[mt], bhi);
                    mma_tf32(acc[mt][nt], ahi[mt], blo);
                    mma_tf32(acc[mt][nt], alo[mt], bhi);
                }
            }
        }
        __syncthreads();
    }

#pragma unroll
    for (int mt = 0; mt < 2; mt++) {
#pragma unroll
        for (int nt = 0; nt < 8; nt++) {
            int gm  = bRow + wm * 32 + mt * 16 + gid;
            int col = bCol + wn * 64 + nt * 8 + tg * 2;
            if (gm < NN)
                *(float2*)&C[(size_t)gm * H3 + col] =
                    make_float2(acc[mt][nt][0], acc[mt][nt][1]);
            if (gm + 8 < NN)
                *(float2*)&C[(size_t)(gm + 8) * H3 + col] =
                    make_float2(acc[mt][nt][2], acc[mt][nt][3]);
        }
    }
}

// ---------------- small GEMM layer 4 ----------------
__global__ void k_gemm_small(const float* __restrict__ Hm, const float* __restrict__ Wc,
                             float* __restrict__ G4) {
    int warp = (blockIdx.x * blockDim.x + threadIdx.x) >> 5;
    int lane = threadIdx.x & 31;
    if (warp >= NN) return;
    float acc[6] = {0.f, 0.f, 0.f, 0.f, 0.f, 0.f};
    for (int k = lane; k < 128; k += 32) {
        float h = Hm[(size_t)warp * 128 + k];
#pragma unroll
        for (int c = 0; c < 6; c++) acc[c] += h * Wc[k * 6 + c];
    }
#pragma unroll
    for (int off = 16; off; off >>= 1)
#pragma unroll
        for (int c = 0; c < 6; c++)
            acc[c] += __shfl_down_sync(0xffffffffu, acc[c], off);
    if (lane == 0) {
#pragma unroll
        for (int c = 0; c < 6; c++) G4[(size_t)warp * 6 + c] = acc[c];
    }
}

// ---------------- spmv width-128, warp per node, float4 lanes ----------------
__global__ void k_spmv128w(const float* __restrict__ v, int vs, int vo,
                           const float* __restrict__ add, int as_, int ao,
                           const float* __restrict__ bias,
                           float* __restrict__ outp, int os, int oo, int doRelu) {
    int idx  = blockIdx.x * blockDim.x + threadIdx.x;
    int warp = idx >> 5;
    int lane = idx & 31;
    if (warp >= NN) return;
    int s = g_rowptr[warp];
    int e = g_rowptr[warp + 1];
    float4 acc = make_float4(0.f, 0.f, 0.f, 0.f);
    for (int i = s; i < e; i++) {
        float w = g_cw[i];
        float4 t = *(const float4*)(v + (size_t)g_csrc[i] * vs + vo + lane * 4);
        acc.x = fmaf(w, t.x, acc.x);
        acc.y = fmaf(w, t.y, acc.y);
        acc.z = fmaf(w, t.z, acc.z);
        acc.w = fmaf(w, t.w, acc.w);
    }
    float4 a = *(const float4*)(add + (size_t)warp * as_ + ao + lane * 4);
    acc.x += a.x; acc.y += a.y; acc.z += a.z; acc.w += a.w;
    if (bias) {
        float4 bb = *(const float4*)(bias + lane * 4);
        acc.x += bb.x; acc.y += bb.y; acc.z += bb.z; acc.w += bb.w;
    }
    if (doRelu) {
        acc.x = fminf(fmaxf(acc.x, 0.f), 6.f);
        acc.y = fminf(fmaxf(acc.y, 0.f), 6.f);
        acc.z = fminf(fmaxf(acc.z, 0.f), 6.f);
        acc.w = fminf(fmaxf(acc.w, 0.f), 6.f);
    }
    *(float4*)(outp + (size_t)warp * os + oo + lane * 4) = acc;
}

// ---------------- spmv width-2 (layer 4) ----------------
__global__ void k_spmv2(const float* __restrict__ v, int vs, int vo,
                        const float* __restrict__ add, int as_, int ao,
                        const float* __restrict__ bias,
                        float* __restrict__ outp, int os, int oo) {
    int n = blockIdx.x * blockDim.x + threadIdx.x;
    if (n >= NN) return;
    int s = g_rowptr[n];
    int e = g_rowptr[n + 1];
    float a0 = 0.f, a1 = 0.f;
    for (int i = s; i < e; i++) {
        float w = g_cw[i];
        const float* row = v + (size_t)g_csrc[i] * vs + vo;
        a0 += w * row[0];
        a1 += w * row[1];
    }
    a0 += add[(size_t)n * as_ + ao];
    a1 += add[(size_t)n * as_ + ao + 1];
    if (bias) { a0 += bias[0]; a1 += bias[1]; }
    outp[(size_t)n * os + oo]     = a0;
    outp[(size_t)n * os + oo + 1] = a1;
}

// ---------------- edge tail ----------------
__global__ void k_edgecast(const void* __restrict__ ei, float* __restrict__ out) {
    int i = blockIdx.x * blockDim.x + threadIdx.x;
    if (i < 2 * NE) out[i] = (float)edge_val(ei, i);
}

// ---------------- launch ----------------
extern "C" void kernel_launch(void* const* d_in, const int* in_sizes, int n_in,
                              void* d_out, int out_size) {
    const float* x  = (const float*)d_in[0];
    const void*  ei = d_in[1];
    const float* W1 = (const float*)d_in[2];
    const float* b1 = (const float*)d_in[3];
    const float* W2 = (const float*)d_in[4];
    const float* b2 = (const float*)d_in[5];
    const float* W3 = (const float*)d_in[6];
    const float* b3 = (const float*)d_in[7];
    const float* W4 = (const float*)d_in[8];
    const float* b4 = (const float*)d_in[9];
    float* out = (float*)d_out;

    float *G, *Z, *HA, *HB, *Wc1, *Wc2, *Wc3, *Wc4;
    cudaGetSymbolAddress((void**)&G,  g_G);
    cudaGetSymbolAddress((void**)&Z,  g_Z);
    cudaGetSymbolAddress((void**)&HA, g_HA);
    cudaGetSymbolAddress((void**)&HB, g_HB);
    cudaGetSymbolAddress((void**)&Wc1, g_Wc1);
    cudaGetSymbolAddress((void**)&Wc2, g_Wc2);
    cudaGetSymbolAddress((void**)&Wc3, g_Wc3);
    cudaGetSymbolAddress((void**)&Wc4, g_Wc4);

    // dtype detect + CSR build + weight prep
    k_detect<<<1, 32>>>((const int*)ei);
    k_zero_deg<<<(NN + 255) / 256, 256>>>();
    k_deg<<<(NE + 255) / 256, 256>>>(ei);
    k_dis<<<(NN + 255) / 256, 256>>>();
    k_scan<<<1, 1024>>>();
    k_scatter<<<(NE + 255) / 256, 256>>>(ei);
    k_prepw<<<(165 * H3 + 255) / 256, 256>>>(W1, 165, H, Wc1);
    k_prepw<<<(128 * H3 + 255) / 256, 256>>>(W2, 128, H, Wc2);
    k_prepw<<<(128 * H3 + 255) / 256, 256>>>(W3, 128, H, Wc3);
    k_prepw<<<(128 * 6 + 255) / 256, 256>>>(W4, 128, 2, Wc4);

    dim3 gemmGrid((NN + 127) / 128, H3 / 128);
    int spmvBlocks = (NN * 32 + 255) / 256;

    // layer 1: x[N,165] -> HA
    k_gemm_tc<<<gemmGrid, 256>>>(x, 165, Wc1, G);
    k_spmv128w<<<spmvBlocks, 256>>>(G, H3, 2 * H, G, H3, H, nullptr, Z, H, 0, 0);
    k_spmv128w<<<spmvBlocks, 256>>>(Z, H, 0, G, H3, 0, b1, HA, H, 0, 1);

    // layer 2: HA -> HB
    k_gemm_tc<<<gemmGrid, 256>>>(HA, 128, Wc2, G);
    k_spmv128w<<<spmvBlocks, 256>>>(G, H3, 2 * H, G, H3, H, nullptr, Z, H, 0, 0);
    k_spmv128w<<<spmvBlocks, 256>>>(Z, H, 0, G, H3, 0, b2, HB, H, 0, 1);

    // layer 3: HB -> HA
    k_gemm_tc<<<gemmGrid, 256>>>(HB, 128, Wc3, G);
    k_spmv128w<<<spmvBlocks, 256>>>(G, H3, 2 * H, G, H3, H, nullptr, Z, H, 0, 0);
    k_spmv128w<<<spmvBlocks, 256>>>(Z, H, 0, G, H3, 0, b3, HA, H, 0, 1);

    // layer 4: HA -> out[N,2]
    k_gemm_small<<<spmvBlocks, 256>>>(HA, Wc4, G);
    k_spmv2<<<(NN + 255) / 256, 256>>>(G, 6, 4, G, 6, 2, nullptr, Z, 2, 0);
    k_spmv2<<<(NN + 255) / 256, 256>>>(Z, 2, 0, G, 6, 0, b4, out, 2, 0);

    // edge_index tail of the flattened output tuple
    long long tail = (long long)out_size - 2 * NN;
    if (tail == 2 * NE) {
        k_edgecast<<<(2 * NE + 255) / 256, 256>>>(ei, out + 2 * NN);
    } else if (tail == 4 * NE) {
        cudaMemcpyAsync(out + 2 * NN, ei, (size_t)2 * NE * sizeof(long long),
                        cudaMemcpyDeviceToDevice);
    }
}

// round 5
// speedup vs baseline: 2.5184x; 1.1192x over previous
#include <cuda_runtime.h>
#include <stdint.h>

#define NN 100000
#define NE 625000
#define H  128
#define H3 384

// ---------------- static device scratch ----------------
__device__ int   g_is64;
__device__ int   g_deg[NN];
__device__ float g_dis[NN];
__device__ int   g_rowptr[NN + 1];
__device__ int   g_cursor[NN];
__device__ int   g_csrc[NE];
__device__ __align__(16) float g_cw[NE];
__device__ __align__(16) float g_G0[(size_t)NN * H];
__device__ __align__(16) float g_G1[(size_t)NN * H];
__device__ __align__(16) float g_G2[(size_t)NN * H];
__device__ __align__(16) float g_Z[(size_t)NN * H];
__device__ __align__(16) float g_HA[(size_t)NN * H];
__device__ __align__(16) float g_HB[(size_t)NN * H];
__device__ __align__(16) float g_Wc1[165 * H3];   // 3 segments of [F,128]
__device__ __align__(16) float g_Wc2[128 * H3];
__device__ __align__(16) float g_Wc3[128 * H3];
__device__ __align__(16) float g_Wc4[128 * 6];
__device__ __align__(16) float g_G4[(size_t)NN * 6];
__device__ __align__(16) float g_Z2[(size_t)NN * 2];

__device__ __forceinline__ long long edge_val(const void* ei, long long idx) {
    if (g_is64) return ((const long long*)ei)[idx];
    return (long long)((const int*)ei)[idx];
}

// ---------------- dtype detection ----------------
__global__ void k_detect(const int* __restrict__ ei32) {
    if (threadIdx.x == 0 && blockIdx.x == 0) {
        int all_zero = 1;
        for (int i = 0; i < 128; i++)
            if (ei32[2 * i + 1] != 0) { all_zero = 0; break; }
        g_is64 = all_zero;
    }
}

// ---------------- CSR build ----------------
__global__ void k_zero_deg() {
    int i = blockIdx.x * blockDim.x + threadIdx.x;
    if (i < NN) g_deg[i] = 0;
}

__global__ void k_deg(const void* __restrict__ ei) {
    int e = blockIdx.x * blockDim.x + threadIdx.x;
    if (e < NE) {
        long long d = edge_val(ei, (long long)NE + e);
        if (d >= 0 && d < NN) atomicAdd(&g_deg[(int)d], 1);
    }
}

__global__ void k_dis() {
    int i = blockIdx.x * blockDim.x + threadIdx.x;
    if (i < NN) {
        int d = g_deg[i];
        g_dis[i] = (d > 0) ? rsqrtf((float)d) : 0.0f;
    }
}

__global__ void k_scan() {
    __shared__ int warpsum[32];
    __shared__ int carry;
    __shared__ int chunktotal;
    int tid = threadIdx.x, lane = tid & 31, wid = tid >> 5;
    if (tid == 0) carry = 0;
    __syncthreads();
    for (int base = 0; base < NN; base += 1024) {
        int i = base + tid;
        int v = (i < NN) ? g_deg[i] : 0;
        int inc = v;
#pragma unroll
        for (int off = 1; off < 32; off <<= 1) {
            int t = __shfl_up_sync(0xffffffffu, inc, off);
            if (lane >= off) inc += t;
        }
        if (lane == 31) warpsum[wid] = inc;
        __syncthreads();
        if (wid == 0) {
            int s = warpsum[lane];
            int si = s;
#pragma unroll
            for (int off = 1; off < 32; off <<= 1) {
                int t = __shfl_up_sync(0xffffffffu, si, off);
                if (lane >= off) si += t;
            }
            warpsum[lane] = si - s;
            if (lane == 31) chunktotal = si;
        }
        __syncthreads();
        int excl = carry + warpsum[wid] + inc - v;
        if (i < NN) { g_rowptr[i] = excl; g_cursor[i] = excl; }
        __syncthreads();
        if (tid == 0) carry += chunktotal;
        __syncthreads();
    }
    if (threadIdx.x == 0) g_rowptr[NN] = carry;
}

__global__ void k_scatter(const void* __restrict__ ei) {
    int e = blockIdx.x * blockDim.x + threadIdx.x;
    if (e < NE) {
        long long sl = edge_val(ei, e);
        long long dl = edge_val(ei, (long long)NE + e);
        if (sl < 0 || sl >= NN || dl < 0 || dl >= NN) return;
        int s = (int)sl, d = (int)dl;
        int pos = atomicAdd(&g_cursor[d], 1);
        if (pos >= 0 && pos < NE) {
            g_csrc[pos] = s;
            g_cw[pos]   = -g_dis[s] * g_dis[d];
        }
    }
}

// ---------------- combined-weight prep: seg layout [seg][F][H] ----------------
__global__ void k_prepw(const float* __restrict__ W, int F, int Hh, float* __restrict__ Wc) {
    int t = blockIdx.x * blockDim.x + threadIdx.x;
    int tot = F * 3 * Hh;
    if (t >= tot) return;
    int seg = t / (F * Hh);
    int r = t - seg * F * Hh;
    int f = r / Hh;
    int c = r - f * Hh;
    float v;
    if (seg == 0)      v = W[(0 * F + f) * Hh + c] - W[(2 * F + f) * Hh + c];
    else if (seg == 1) v = W[(1 * F + f) * Hh + c];
    else               v = 2.0f * W[(2 * F + f) * Hh + c];
    Wc[(size_t)seg * F * Hh + (size_t)f * Hh + c] = v;
}

// layer-4 weights interleaved [128][6]: c0..c5 = (W0-W2, W1, 2W2) x 2 cols
__global__ void k_prepw4(const float* __restrict__ W, float* __restrict__ Wc) {
    int t = blockIdx.x * blockDim.x + threadIdx.x;
    if (t >= 128 * 6) return;
    int f = t / 6;
    int r = t - f * 6;
    int seg = r >> 1;
    int c = r & 1;
    float v;
    if (seg == 0)      v = W[(0 * 128 + f) * 2 + c] - W[(2 * 128 + f) * 2 + c];
    else if (seg == 1) v = W[(1 * 128 + f) * 2 + c];
    else               v = 2.0f * W[(2 * 128 + f) * 2 + c];
    Wc[f * 6 + r] = v;
}

// ---------------- tf32 helpers ----------------
__device__ __forceinline__ void split_tf32(float x, uint32_t& hi, uint32_t& lo) {
    uint32_t h;
    asm("cvt.rna.tf32.f32 %0, %1;" : "=r"(h) : "f"(x));
    float l = x - __uint_as_float(h);
    uint32_t lw;
    asm("cvt.rna.tf32.f32 %0, %1;" : "=r"(lw) : "f"(l));
    hi = h; lo = lw;
}

__device__ __forceinline__ void mma_tf32(float* c, const uint32_t* a, const uint32_t* b) {
    asm volatile(
        "mma.sync.aligned.m16n8k8.row.col.f32.tf32.tf32.f32 "
        "{%0,%1,%2,%3}, {%4,%5,%6,%7}, {%8,%9}, {%0,%1,%2,%3};"
        : "+f"(c[0]), "+f"(c[1]), "+f"(c[2]), "+f"(c[3])
        : "r"(a[0]), "r"(a[1]), "r"(a[2]), "r"(a[3]), "r"(b[0]), "r"(b[1]));
}

// ---------------- tensor-core GEMM: Cseg[NN,128] = A[NN,F] @ Bseg[F,128] ----------------
// block tile 128x128, 8 warps 4(M)x2(N), warp tile 32x64, split-tf32 hoisted to smem
#define ASTR 20
#define BSTR 136

__global__ __launch_bounds__(256, 2) void k_gemm_tc(
    const float* __restrict__ A, int F,
    const float* __restrict__ B,
    float* __restrict__ C0, float* __restrict__ C1, float* __restrict__ C2)
{
    __shared__ uint32_t As_hi[128 * ASTR];
    __shared__ uint32_t As_lo[128 * ASTR];
    __shared__ uint32_t Bs_hi[16 * BSTR];
    __shared__ uint32_t Bs_lo[16 * BSTR];

    int tid  = threadIdx.x;
    int wid  = tid >> 5, lane = tid & 31;
    int gid  = lane >> 2, tg = lane & 3;
    int wm   = wid & 3;
    int wn   = wid >> 2;
    int bRow = blockIdx.x * 128;

    const float* Bseg = B + (size_t)blockIdx.y * F * H;
    float* Cseg = (blockIdx.y == 0) ? C0 : ((blockIdx.y == 1) ? C1 : C2);

    float acc[2][8][4];
#pragma unroll
    for (int i = 0; i < 2; i++)
#pragma unroll
        for (int j = 0; j < 8; j++)
#pragma unroll
            for (int k = 0; k < 4; k++) acc[i][j][k] = 0.f;

    for (int k0 = 0; k0 < F; k0 += 16) {
        // A tile 128x16, split to hi/lo in smem
#pragma unroll
        for (int t = 0; t < 8; t++) {
            int l = tid + t * 256;
            int m = l >> 4, k = l & 15;
            int gm = bRow + m, gk = k0 + k;
            float v = 0.f;
            if (gm < NN && gk < F) v = A[(size_t)gm * F + gk];
            uint32_t hi, lo;
            split_tf32(v, hi, lo);
            As_hi[m * ASTR + k] = hi;
            As_lo[m * ASTR + k] = lo;
        }
        // B tile 16x128 (float4 global load), split to hi/lo
#pragma unroll
        for (int t = 0; t < 2; t++) {
            int l = tid + t * 256;
            int kr = l >> 5, c4 = l & 31;
            int gk = k0 + kr;
            float4 v = make_float4(0.f, 0.f, 0.f, 0.f);
            if (gk < F) v = *(const float4*)&Bseg[(size_t)gk * H + c4 * 4];
            uint32_t hx, lx, hy, ly, hz, lz, hw, lw;
            split_tf32(v.x, hx, lx);
            split_tf32(v.y, hy, ly);
            split_tf32(v.z, hz, lz);
            split_tf32(v.w, hw, lw);
            int o = kr * BSTR + c4 * 4;
            Bs_hi[o] = hx; Bs_hi[o + 1] = hy; Bs_hi[o + 2] = hz; Bs_hi[o + 3] = hw;
            Bs_lo[o] = lx; Bs_lo[o + 1] = ly; Bs_lo[o + 2] = lz; Bs_lo[o + 3] = lw;
        }
        __syncthreads();

#pragma unroll
        for (int k8 = 0; k8 < 16; k8 += 8) {
            uint32_t ahi[2][4], alo[2][4];
#pragma unroll
            for (int mt = 0; mt < 2; mt++) {
                int m = wm * 32 + mt * 16 + gid;
                ahi[mt][0] = As_hi[m * ASTR + k8 + tg];
                ahi[mt][1] = As_hi[(m + 8) * ASTR + k8 + tg];
                ahi[mt][2] = As_hi[m * ASTR + k8 + tg + 4];
                ahi[mt][3] = As_hi[(m + 8) * ASTR + k8 + tg + 4];
                alo[mt][0] = As_lo[m * ASTR + k8 + tg];
                alo[mt][1] = As_lo[(m + 8) * ASTR + k8 + tg];
                alo[mt][2] = As_lo[m * ASTR + k8 + tg + 4];
                alo[mt][3] = As_lo[(m + 8) * ASTR + k8 + tg + 4];
            }
#pragma unroll
            for (int nt = 0; nt < 8; nt++) {
                int n = wn * 64 + nt * 8 + gid;
                uint32_t bhi[2], blo[2];
                bhi[0] = Bs_hi[(k8 + tg) * BSTR + n];
                bhi[1] = Bs_hi[(k8 + tg + 4) * BSTR + n];
                blo[0] = Bs_lo[(k8 + tg) * BSTR + n];
                blo[1] = Bs_lo[(k8 + tg + 4) * BSTR + n];
#pragma unroll
                for (int mt = 0; mt < 2; mt++) {
                    mma_tf32(acc[mt][nt], ahi[mt], bhi);
                    mma_tf32(acc[mt][nt], ahi[mt], blo);
                    mma_tf32(acc[mt][nt], alo[mt], bhi);
                }
            }
        }
        __syncthreads();
    }

#pragma unroll
    for (int mt = 0; mt < 2; mt++) {
#pragma unroll
        for (int nt = 0; nt < 8; nt++) {
            int gm  = bRow + wm * 32 + mt * 16 + gid;
            int col = wn * 64 + nt * 8 + tg * 2;
            if (gm < NN)
                *(float2*)&Cseg[(size_t)gm * H + col] =
                    make_float2(acc[mt][nt][0], acc[mt][nt][1]);
            if (gm + 8 < NN)
                *(float2*)&Cseg[(size_t)(gm + 8) * H + col] =
                    make_float2(acc[mt][nt][2], acc[mt][nt][3]);
        }
    }
}

// ---------------- small GEMM layer 4: G4[N,6] = Hm[N,128] @ Wc4[128,6] ----------------
__global__ void k_gemm_small(const float* __restrict__ Hm, const float* __restrict__ Wc,
                             float* __restrict__ G4) {
    int warp = (blockIdx.x * blockDim.x + threadIdx.x) >> 5;
    int lane = threadIdx.x & 31;
    if (warp >= NN) return;
    float acc[6] = {0.f, 0.f, 0.f, 0.f, 0.f, 0.f};
    for (int k = lane; k < 128; k += 32) {
        float h = Hm[(size_t)warp * 128 + k];
#pragma unroll
        for (int c = 0; c < 6; c++) acc[c] += h * Wc[k * 6 + c];
    }
#pragma unroll
    for (int off = 16; off; off >>= 1)
#pragma unroll
        for (int c = 0; c < 6; c++)
            acc[c] += __shfl_down_sync(0xffffffffu, acc[c], off);
    if (lane == 0) {
#pragma unroll
        for (int c = 0; c < 6; c++) G4[(size_t)warp * 6 + c] = acc[c];
    }
}

// ---------------- spmv width-128: warp per node, shfl-broadcast edges ----------------
// out[n] = sum_e w * v[src_e] + add[n] (+bias, relu6); all matrices [N,128]
__global__ void k_spmv128w(const float* __restrict__ v,
                           const float* __restrict__ add,
                           const float* __restrict__ bias,
                           float* __restrict__ outp, int doRelu) {
    int idx  = blockIdx.x * blockDim.x + threadIdx.x;
    int warp = idx >> 5;
    int lane = idx & 31;
    if (warp >= NN) return;
    int s = g_rowptr[warp];
    int e = g_rowptr[warp + 1];

    float4 acc = *(const float4*)(add + (size_t)warp * H + lane * 4);
    if (bias) {
        float4 bb = *(const float4*)(bias + lane * 4);
        acc.x += bb.x; acc.y += bb.y; acc.z += bb.z; acc.w += bb.w;
    }

    for (int base = s; base < e; base += 32) {
        int cnt = e - base; if (cnt > 32) cnt = 32;
        int   myi = 0;
        float myw = 0.f;
        if (lane < cnt) { myi = g_csrc[base + lane]; myw = g_cw[base + lane]; }
        for (int j = 0; j < cnt; j++) {
            int   src = __shfl_sync(0xffffffffu, myi, j);
            float w   = __shfl_sync(0xffffffffu, myw, j);
            float4 t = *(const float4*)(v + (size_t)src * H + lane * 4);
            acc.x = fmaf(w, t.x, acc.x);
            acc.y = fmaf(w, t.y, acc.y);
            acc.z = fmaf(w, t.z, acc.z);
            acc.w = fmaf(w, t.w, acc.w);
        }
    }
    if (doRelu) {
        acc.x = fminf(fmaxf(acc.x, 0.f), 6.f);
        acc.y = fminf(fmaxf(acc.y, 0.f), 6.f);
        acc.z = fminf(fmaxf(acc.z, 0.f), 6.f);
        acc.w = fminf(fmaxf(acc.w, 0.f), 6.f);
    }
    *(float4*)(outp + (size_t)warp * H + lane * 4) = acc;
}

// ---------------- spmv width-2 (layer 4) ----------------
__global__ void k_spmv2(const float* __restrict__ v, int vs, int vo,
                        const float* __restrict__ add, int as_, int ao,
                        const float* __restrict__ bias,
                        float* __restrict__ outp, int os, int oo) {
    int n = blockIdx.x * blockDim.x + threadIdx.x;
    if (n >= NN) return;
    int s = g_rowptr[n];
    int e = g_rowptr[n + 1];
    float a0 = 0.f, a1 = 0.f;
    for (int i = s; i < e; i++) {
        float w = g_cw[i];
        const float* row = v + (size_t)g_csrc[i] * vs + vo;
        a0 += w * row[0];
        a1 += w * row[1];
    }
    a0 += add[(size_t)n * as_ + ao];
    a1 += add[(size_t)n * as_ + ao + 1];
    if (bias) { a0 += bias[0]; a1 += bias[1]; }
    outp[(size_t)n * os + oo]     = a0;
    outp[(size_t)n * os + oo + 1] = a1;
}

// ---------------- edge tail ----------------
__global__ void k_edgecast(const void* __restrict__ ei, float* __restrict__ out) {
    int i = blockIdx.x * blockDim.x + threadIdx.x;
    if (i < 2 * NE) out[i] = (float)edge_val(ei, i);
}

// ---------------- launch ----------------
extern "C" void kernel_launch(void* const* d_in, const int* in_sizes, int n_in,
                              void* d_out, int out_size) {
    const float* x  = (const float*)d_in[0];
    const void*  ei = d_in[1];
    const float* W1 = (const float*)d_in[2];
    const float* b1 = (const float*)d_in[3];
    const float* W2 = (const float*)d_in[4];
    const float* b2 = (const float*)d_in[5];
    const float* W3 = (const float*)d_in[6];
    const float* b3 = (const float*)d_in[7];
    const float* W4 = (const float*)d_in[8];
    const float* b4 = (const float*)d_in[9];
    float* out = (float*)d_out;

    float *G0, *G1, *G2, *Z, *HA, *HB, *Wc1, *Wc2, *Wc3, *Wc4, *G4, *Z2;
    cudaGetSymbolAddress((void**)&G0, g_G0);
    cudaGetSymbolAddress((void**)&G1, g_G1);
    cudaGetSymbolAddress((void**)&G2, g_G2);
    cudaGetSymbolAddress((void**)&Z,  g_Z);
    cudaGetSymbolAddress((void**)&HA, g_HA);
    cudaGetSymbolAddress((void**)&HB, g_HB);
    cudaGetSymbolAddress((void**)&Wc1, g_Wc1);
    cudaGetSymbolAddress((void**)&Wc2, g_Wc2);
    cudaGetSymbolAddress((void**)&Wc3, g_Wc3);
    cudaGetSymbolAddress((void**)&Wc4, g_Wc4);
    cudaGetSymbolAddress((void**)&G4, g_G4);
    cudaGetSymbolAddress((void**)&Z2, g_Z2);

    // dtype detect + CSR build + weight prep
    k_detect<<<1, 32>>>((const int*)ei);
    k_zero_deg<<<(NN + 255) / 256, 256>>>();
    k_deg<<<(NE + 255) / 256, 256>>>(ei);
    k_dis<<<(NN + 255) / 256, 256>>>();
    k_scan<<<1, 1024>>>();
    k_scatter<<<(NE + 255) / 256, 256>>>(ei);
    k_prepw<<<(165 * H3 + 255) / 256, 256>>>(W1, 165, H, Wc1);
    k_prepw<<<(128 * H3 + 255) / 256, 256>>>(W2, 128, H, Wc2);
    k_prepw<<<(128 * H3 + 255) / 256, 256>>>(W3, 128, H, Wc3);
    k_prepw4<<<(128 * 6 + 255) / 256, 256>>>(W4, Wc4);

    dim3 gemmGrid((NN + 127) / 128, 3);
    int spmvBlocks = (NN * 32 + 255) / 256;

    // layer 1: x[N,165] -> HA
    k_gemm_tc<<<gemmGrid, 256>>>(x, 165, Wc1, G0, G1, G2);
    k_spmv128w<<<spmvBlocks, 256>>>(G2, G1, nullptr, Z, 0);
    k_spmv128w<<<spmvBlocks, 256>>>(Z, G0, b1, HA, 1);

    // layer 2: HA -> HB
    k_gemm_tc<<<gemmGrid, 256>>>(HA, 128, Wc2, G0, G1, G2);
    k_spmv128w<<<spmvBlocks, 256>>>(G2, G1, nullptr, Z, 0);
    k_spmv128w<<<spmvBlocks, 256>>>(Z, G0, b2, HB, 1);

    // layer 3: HB -> HA
    k_gemm_tc<<<gemmGrid, 256>>>(HB, 128, Wc3, G0, G1, G2);
    k_spmv128w<<<spmvBlocks, 256>>>(G2, G1, nullptr, Z, 0);
    k_spmv128w<<<spmvBlocks, 256>>>(Z, G0, b3, HA, 1);

    // layer 4: HA -> out[N,2]
    k_gemm_small<<<spmvBlocks, 256>>>(HA, Wc4, G4);
    k_spmv2<<<(NN + 255) / 256, 256>>>(G4, 6, 4, G4, 6, 2, nullptr, Z2, 2, 0);
    k_spmv2<<<(NN + 255) / 256, 256>>>(Z2, 2, 0, G4, 6, 0, b4, out, 2, 0);

    // edge_index tail of the flattened output tuple
    long long tail = (long long)out_size - 2 * NN;
    if (tail == 2 * NE) {
        k_edgecast<<<(2 * NE + 255) / 256, 256>>>(ei, out + 2 * NN);
    } else if (tail == 4 * NE) {
        cudaMemcpyAsync(out + 2 * NN, ei, (size_t)2 * NE * sizeof(long long),
                        cudaMemcpyDeviceToDevice);
    }
}

// round 6
// speedup vs baseline: 2.5391x; 1.0083x over previous
#include <cuda_runtime.h>
#include <stdint.h>

#define NN 100000
#define NE 625000
#define H  128
#define H3 384

// ---------------- static device scratch ----------------
__device__ int   g_is64;
__device__ int   g_deg[NN];
__device__ float g_dis[NN];
__device__ int   g_rowptr[NN + 1];
__device__ int   g_cursor[NN];
__device__ __align__(16) int2  g_edge[NE];     // (src, w bits)
__device__ __align__(16) float g_G0[(size_t)NN * H];
__device__ __align__(16) float g_G1[(size_t)NN * H];
__device__ __align__(16) float g_G2[(size_t)NN * H];
__device__ __align__(16) float g_Z[(size_t)NN * H];
__device__ __align__(16) float g_HA[(size_t)NN * H];
__device__ __align__(16) float g_HB[(size_t)NN * H];
__device__ __align__(16) float g_Wc1[165 * H3];   // 3 segments of [F,128]
__device__ __align__(16) float g_Wc2[128 * H3];
__device__ __align__(16) float g_Wc3[128 * H3];
__device__ __align__(16) float g_Wc4[128 * 6];
__device__ __align__(16) float g_G4[(size_t)NN * 6];
__device__ __align__(16) float g_Z2[(size_t)NN * 2];

__device__ __forceinline__ long long edge_val(const void* ei, long long idx) {
    if (g_is64) return ((const long long*)ei)[idx];
    return (long long)((const int*)ei)[idx];
}

// ---------------- zero deg + dtype detect (thread 0 of block 0) ----------------
__global__ void k_zero_detect(const int* __restrict__ ei32) {
    int i = blockIdx.x * blockDim.x + threadIdx.x;
    if (i < NN) g_deg[i] = 0;
    if (i == 0) {
        int all_zero = 1;
        for (int t = 0; t < 128; t++)
            if (ei32[2 * t + 1] != 0) { all_zero = 0; break; }
        g_is64 = all_zero;
    }
}

__global__ void k_deg(const void* __restrict__ ei) {
    int e = blockIdx.x * blockDim.x + threadIdx.x;
    if (e < NE) {
        long long d = edge_val(ei, (long long)NE + e);
        if (d >= 0 && d < NN) atomicAdd(&g_deg[(int)d], 1);
    }
}

__global__ void k_dis() {
    int i = blockIdx.x * blockDim.x + threadIdx.x;
    if (i < NN) {
        int d = g_deg[i];
        g_dis[i] = (d > 0) ? rsqrtf((float)d) : 0.0f;
    }
}

// single-block scan, 4 elements/thread (int4), 25 chunks
__global__ void k_scan() {
    __shared__ int warpsum[32];
    __shared__ int carry;
    __shared__ int chunktotal;
    int tid = threadIdx.x, lane = tid & 31, wid = tid >> 5;
    if (tid == 0) carry = 0;
    __syncthreads();
    for (int base = 0; base < NN; base += 4096) {
        int i0 = base + tid * 4;
        int v0 = 0, v1 = 0, v2 = 0, v3 = 0;
        if (i0 + 3 < NN) {
            int4 q = *(const int4*)&g_deg[i0];
            v0 = q.x; v1 = q.y; v2 = q.z; v3 = q.w;
        } else {
            if (i0 < NN)     v0 = g_deg[i0];
            if (i0 + 1 < NN) v1 = g_deg[i0 + 1];
            if (i0 + 2 < NN) v2 = g_deg[i0 + 2];
            if (i0 + 3 < NN) v3 = g_deg[i0 + 3];
        }
        int tsum = v0 + v1 + v2 + v3;
        int inc = tsum;
#pragma unroll
        for (int off = 1; off < 32; off <<= 1) {
            int t = __shfl_up_sync(0xffffffffu, inc, off);
            if (lane >= off) inc += t;
        }
        if (lane == 31) warpsum[wid] = inc;
        __syncthreads();
        if (wid == 0) {
            int s = warpsum[lane];
            int si = s;
#pragma unroll
            for (int off = 1; off < 32; off <<= 1) {
                int t = __shfl_up_sync(0xffffffffu, si, off);
                if (lane >= off) si += t;
            }
            warpsum[lane] = si - s;
            if (lane == 31) chunktotal = si;
        }
        __syncthreads();
        int start = carry + warpsum[wid] + inc - tsum;
        if (i0 < NN)     { g_rowptr[i0] = start;     g_cursor[i0] = start; }
        start += v0;
        if (i0 + 1 < NN) { g_rowptr[i0 + 1] = start; g_cursor[i0 + 1] = start; }
        start += v1;
        if (i0 + 2 < NN) { g_rowptr[i0 + 2] = start; g_cursor[i0 + 2] = start; }
        start += v2;
        if (i0 + 3 < NN) { g_rowptr[i0 + 3] = start; g_cursor[i0 + 3] = start; }
        __syncthreads();
        if (tid == 0) carry += chunktotal;
        __syncthreads();
    }
    if (threadIdx.x == 0) g_rowptr[NN] = carry;
}

__global__ void k_scatter(const void* __restrict__ ei) {
    int e = blockIdx.x * blockDim.x + threadIdx.x;
    if (e < NE) {
        long long sl = edge_val(ei, e);
        long long dl = edge_val(ei, (long long)NE + e);
        if (sl < 0 || sl >= NN || dl < 0 || dl >= NN) return;
        int s = (int)sl, d = (int)dl;
        int pos = atomicAdd(&g_cursor[d], 1);
        if (pos >= 0 && pos < NE) {
            float w = -g_dis[s] * g_dis[d];
            g_edge[pos] = make_int2(s, __float_as_int(w));
        }
    }
}

// ---------------- merged combined-weight prep ----------------
// Wc layouts: [seg][F][H] for layers 1-3; layer4 interleaved [128][6]
__device__ __forceinline__ void prep_one(const float* W, int F, int Hh, float* Wc, int t) {
    int seg = t / (F * Hh);
    int r = t - seg * F * Hh;
    int f = r / Hh;
    int c = r - f * Hh;
    float v;
    if (seg == 0)      v = W[(0 * F + f) * Hh + c] - W[(2 * F + f) * Hh + c];
    else if (seg == 1) v = W[(1 * F + f) * Hh + c];
    else               v = 2.0f * W[(2 * F + f) * Hh + c];
    Wc[(size_t)seg * F * Hh + (size_t)f * Hh + c] = v;
}

#define PW1 (165 * H3)
#define PW2 (PW1 + 128 * H3)
#define PW3 (PW2 + 128 * H3)
#define PWT (PW3 + 128 * 6)

__global__ void k_prep_all(const float* __restrict__ W1, const float* __restrict__ W2,
                           const float* __restrict__ W3, const float* __restrict__ W4) {
    int t = blockIdx.x * blockDim.x + threadIdx.x;
    if (t >= PWT) return;
    if (t < PW1)      prep_one(W1, 165, H, g_Wc1, t);
    else if (t < PW2) prep_one(W2, 128, H, g_Wc2, t - PW1);
    else if (t < PW3) prep_one(W3, 128, H, g_Wc3, t - PW2);
    else {
        int u = t - PW3;           // [128][6] interleaved: (W0-W2, W1, 2W2) x 2 cols
        int f = u / 6;
        int r = u - f * 6;
        int seg = r >> 1;
        int c = r & 1;
        float v;
        if (seg == 0)      v = W4[(0 * 128 + f) * 2 + c] - W4[(2 * 128 + f) * 2 + c];
        else if (seg == 1) v = W4[(1 * 128 + f) * 2 + c];
        else               v = 2.0f * W4[(2 * 128 + f) * 2 + c];
        g_Wc4[f * 6 + r] = v;
    }
}

// ---------------- tf32 helpers ----------------
__device__ __forceinline__ void split_tf32(float x, uint32_t& hi, uint32_t& lo) {
    uint32_t h;
    asm("cvt.rna.tf32.f32 %0, %1;" : "=r"(h) : "f"(x));
    float l = x - __uint_as_float(h);
    uint32_t lw;
    asm("cvt.rna.tf32.f32 %0, %1;" : "=r"(lw) : "f"(l));
    hi = h; lo = lw;
}

__device__ __forceinline__ void mma_tf32(float* c, const uint32_t* a, const uint32_t* b) {
    asm volatile(
        "mma.sync.aligned.m16n8k8.row.col.f32.tf32.tf32.f32 "
        "{%0,%1,%2,%3}, {%4,%5,%6,%7}, {%8,%9}, {%0,%1,%2,%3};"
        : "+f"(c[0]), "+f"(c[1]), "+f"(c[2]), "+f"(c[3])
        : "r"(a[0]), "r"(a[1]), "r"(a[2]), "r"(a[3]), "r"(b[0]), "r"(b[1]));
}

// ---------------- tensor-core GEMM with register-prefetch pipeline ----------------
// block tile 128x128, 8 warps 4(M)x2(N), warp tile 32x64, split-tf32 in smem
#define ASTR 20
#define BSTR 136

__global__ __launch_bounds__(256, 2) void k_gemm_tc(
    const float* __restrict__ A, int F,
    const float* __restrict__ B,
    float* __restrict__ C0, float* __restrict__ C1, float* __restrict__ C2)
{
    __shared__ uint32_t As_hi[128 * ASTR];
    __shared__ uint32_t As_lo[128 * ASTR];
    __shared__ uint32_t Bs_hi[16 * BSTR];
    __shared__ uint32_t Bs_lo[16 * BSTR];

    int tid  = threadIdx.x;
    int wid  = tid >> 5, lane = tid & 31;
    int gid  = lane >> 2, tg = lane & 3;
    int wm   = wid & 3;
    int wn   = wid >> 2;
    int bRow = blockIdx.x * 128;

    const float* Bseg = B + (size_t)blockIdx.y * F * H;
    float* Cseg = (blockIdx.y == 0) ? C0 : ((blockIdx.y == 1) ? C1 : C2);

    float acc[2][8][4];
#pragma unroll
    for (int i = 0; i < 2; i++)
#pragma unroll
        for (int j = 0; j < 8; j++)
#pragma unroll
            for (int k = 0; k < 4; k++) acc[i][j][k] = 0.f;

    float  aR[8];
    float4 bR[2];

    // prefetch tile 0 into registers
    {
#pragma unroll
        for (int t = 0; t < 8; t++) {
            int l = tid + t * 256;
            int m = l >> 4, k = l & 15;
            int gm = bRow + m, gk = k;
            aR[t] = (gm < NN && gk < F) ? A[(size_t)gm * F + gk] : 0.f;
        }
#pragma unroll
        for (int t = 0; t < 2; t++) {
            int l = tid + t * 256;
            int kr = l >> 5, c4 = l & 31;
            bR[t] = (kr < F) ? *(const float4*)&Bseg[(size_t)kr * H + c4 * 4]
                             : make_float4(0.f, 0.f, 0.f, 0.f);
        }
    }

    for (int k0 = 0; k0 < F; k0 += 16) {
        // split current registers into smem
#pragma unroll
        for (int t = 0; t < 8; t++) {
            int l = tid + t * 256;
            int m = l >> 4, k = l & 15;
            uint32_t hi, lo;
            split_tf32(aR[t], hi, lo);
            As_hi[m * ASTR + k] = hi;
            As_lo[m * ASTR + k] = lo;
        }
#pragma unroll
        for (int t = 0; t < 2; t++) {
            int l = tid + t * 256;
            int kr = l >> 5, c4 = l & 31;
            uint32_t hx, lx, hy, ly, hz, lz, hw, lw;
            split_tf32(bR[t].x, hx, lx);
            split_tf32(bR[t].y, hy, ly);
            split_tf32(bR[t].z, hz, lz);
            split_tf32(bR[t].w, hw, lw);
            int o = kr * BSTR + c4 * 4;
            Bs_hi[o] = hx; Bs_hi[o + 1] = hy; Bs_hi[o + 2] = hz; Bs_hi[o + 3] = hw;
            Bs_lo[o] = lx; Bs_lo[o + 1] = ly; Bs_lo[o + 2] = lz; Bs_lo[o + 3] = lw;
        }
        __syncthreads();

        // issue next tile's global loads (overlap with MMAs below)
        int kn = k0 + 16;
        if (kn < F) {
#pragma unroll
            for (int t = 0; t < 8; t++) {
                int l = tid + t * 256;
                int m = l >> 4, k = l & 15;
                int gm = bRow + m, gk = kn + k;
                aR[t] = (gm < NN && gk < F) ? A[(size_t)gm * F + gk] : 0.f;
            }
#pragma unroll
            for (int t = 0; t < 2; t++) {
                int l = tid + t * 256;
                int kr = l >> 5, c4 = l & 31;
                int gk = kn + kr;
                bR[t] = (gk < F) ? *(const float4*)&Bseg[(size_t)gk * H + c4 * 4]
                                 : make_float4(0.f, 0.f, 0.f, 0.f);
            }
        }

#pragma unroll
        for (int k8 = 0; k8 < 16; k8 += 8) {
            uint32_t ahi[2][4], alo[2][4];
#pragma unroll
            for (int mt = 0; mt < 2; mt++) {
                int m = wm * 32 + mt * 16 + gid;
                ahi[mt][0] = As_hi[m * ASTR + k8 + tg];
                ahi[mt][1] = As_hi[(m + 8) * ASTR + k8 + tg];
                ahi[mt][2] = As_hi[m * ASTR + k8 + tg + 4];
                ahi[mt][3] = As_hi[(m + 8) * ASTR + k8 + tg + 4];
                alo[mt][0] = As_lo[m * ASTR + k8 + tg];
                alo[mt][1] = As_lo[(m + 8) * ASTR + k8 + tg];
                alo[mt][2] = As_lo[m * ASTR + k8 + tg + 4];
                alo[mt][3] = As_lo[(m + 8) * ASTR + k8 + tg + 4];
            }
#pragma unroll
            for (int nt = 0; nt < 8; nt++) {
                int n = wn * 64 + nt * 8 + gid;
                uint32_t bhi[2], blo[2];
                bhi[0] = Bs_hi[(k8 + tg) * BSTR + n];
                bhi[1] = Bs_hi[(k8 + tg + 4) * BSTR + n];
                blo[0] = Bs_lo[(k8 + tg) * BSTR + n];
                blo[1] = Bs_lo[(k8 + tg + 4) * BSTR + n];
#pragma unroll
                for (int mt = 0; mt < 2; mt++) {
                    mma_tf32(acc[mt][nt], ahi[mt], bhi);
                    mma_tf32(acc[mt][nt], ahi[mt], blo);
                    mma_tf32(acc[mt][nt], alo[mt], bhi);
                }
            }
        }
        __syncthreads();
    }

#pragma unroll
    for (int mt = 0; mt < 2; mt++) {
#pragma unroll
        for (int nt = 0; nt < 8; nt++) {
            int gm  = bRow + wm * 32 + mt * 16 + gid;
            int col = wn * 64 + nt * 8 + tg * 2;
            if (gm < NN)
                *(float2*)&Cseg[(size_t)gm * H + col] =
                    make_float2(acc[mt][nt][0], acc[mt][nt][1]);
            if (gm + 8 < NN)
                *(float2*)&Cseg[(size_t)(gm + 8) * H + col] =
                    make_float2(acc[mt][nt][2], acc[mt][nt][3]);
        }
    }
}

// ---------------- small GEMM layer 4: G4[N,6] = Hm[N,128] @ Wc4[128,6] ----------------
__global__ __launch_bounds__(256) void k_gemm_small(
    const float* __restrict__ Hm, const float* __restrict__ Wc, float* __restrict__ G4) {
    __shared__ float Ws[128 * 6];
    for (int i = threadIdx.x; i < 128 * 6; i += blockDim.x) Ws[i] = Wc[i];
    __syncthreads();
    int warp = (blockIdx.x * blockDim.x + threadIdx.x) >> 5;
    int lane = threadIdx.x & 31;
    if (warp >= NN) return;
    int k = lane * 4;
    float4 h = *(const float4*)(Hm + (size_t)warp * 128 + k);
    float acc[6];
#pragma unroll
    for (int c = 0; c < 6; c++)
        acc[c] = h.x * Ws[k * 6 + c] + h.y * Ws[(k + 1) * 6 + c]
               + h.z * Ws[(k + 2) * 6 + c] + h.w * Ws[(k + 3) * 6 + c];
#pragma unroll
    for (int off = 16; off; off >>= 1)
#pragma unroll
        for (int c = 0; c < 6; c++)
            acc[c] += __shfl_down_sync(0xffffffffu, acc[c], off);
    if (lane == 0) {
#pragma unroll
        for (int c = 0; c < 6; c++) G4[(size_t)warp * 6 + c] = acc[c];
    }
}

// ---------------- spmv width-128: warp per node, packed edges, shfl-broadcast ----------
__global__ void k_spmv128w(const float* __restrict__ v,
                           const float* __restrict__ add,
                           const float* __restrict__ bias,
                           float* __restrict__ outp, int doRelu) {
    int idx  = blockIdx.x * blockDim.x + threadIdx.x;
    int warp = idx >> 5;
    int lane = idx & 31;
    if (warp >= NN) return;
    int s = g_rowptr[warp];
    int e = g_rowptr[warp + 1];

    float4 acc = *(const float4*)(add + (size_t)warp * H + lane * 4);
    if (bias) {
        float4 bb = *(const float4*)(bias + lane * 4);
        acc.x += bb.x; acc.y += bb.y; acc.z += bb.z; acc.w += bb.w;
    }

    for (int base = s; base < e; base += 32) {
        int cnt = e - base; if (cnt > 32) cnt = 32;
        int2 ed = make_int2(0, 0);
        if (lane < cnt) ed = g_edge[base + lane];
        for (int j = 0; j < cnt; j++) {
            int   src = __shfl_sync(0xffffffffu, ed.x, j);
            float w   = __int_as_float(__shfl_sync(0xffffffffu, ed.y, j));
            float4 t = *(const float4*)(v + (size_t)src * H + lane * 4);
            acc.x = fmaf(w, t.x, acc.x);
            acc.y = fmaf(w, t.y, acc.y);
            acc.z = fmaf(w, t.z, acc.z);
            acc.w = fmaf(w, t.w, acc.w);
        }
    }
    if (doRelu) {
        acc.x = fminf(fmaxf(acc.x, 0.f), 6.f);
        acc.y = fminf(fmaxf(acc.y, 0.f), 6.f);
        acc.z = fminf(fmaxf(acc.z, 0.f), 6.f);
        acc.w = fminf(fmaxf(acc.w, 0.f), 6.f);
    }
    *(float4*)(outp + (size_t)warp * H + lane * 4) = acc;
}

// ---------------- spmv width-2 (layer 4) ----------------
__global__ void k_spmv2(const float* __restrict__ v, int vs, int vo,
                        const float* __restrict__ add, int as_, int ao,
                        const float* __restrict__ bias,
                        float* __restrict__ outp, int os, int oo) {
    int n = blockIdx.x * blockDim.x + threadIdx.x;
    if (n >= NN) return;
    int s = g_rowptr[n];
    int e = g_rowptr[n + 1];
    float a0 = 0.f, a1 = 0.f;
    for (int i = s; i < e; i++) {
        int2 ed = g_edge[i];
        float w = __int_as_float(ed.y);
        const float* row = v + (size_t)ed.x * vs + vo;
        a0 += w * row[0];
        a1 += w * row[1];
    }
    a0 += add[(size_t)n * as_ + ao];
    a1 += add[(size_t)n * as_ + ao + 1];
    if (bias) { a0 += bias[0]; a1 += bias[1]; }
    outp[(size_t)n * os + oo]     = a0;
    outp[(size_t)n * os + oo + 1] = a1;
}

// ---------------- edge tail ----------------
__global__ void k_edgecast(const void* __restrict__ ei, float* __restrict__ out) {
    int i = blockIdx.x * blockDim.x + threadIdx.x;
    if (i < 2 * NE) out[i] = (float)edge_val(ei, i);
}

// ---------------- launch ----------------
extern "C" void kernel_launch(void* const* d_in, const int* in_sizes, int n_in,
                              void* d_out, int out_size) {
    const float* x  = (const float*)d_in[0];
    const void*  ei = d_in[1];
    const float* W1 = (const float*)d_in[2];
    const float* b1 = (const float*)d_in[3];
    const float* W2 = (const float*)d_in[4];
    const float* b2 = (const float*)d_in[5];
    const float* W3 = (const float*)d_in[6];
    const float* b3 = (const float*)d_in[7];
    const float* W4 = (const float*)d_in[8];
    const float* b4 = (const float*)d_in[9];
    float* out = (float*)d_out;

    float *G0, *G1, *G2, *Z, *HA, *HB, *Wc1, *Wc2, *Wc3, *Wc4, *G4, *Z2;
    cudaGetSymbolAddress((void**)&G0, g_G0);
    cudaGetSymbolAddress((void**)&G1, g_G1);
    cudaGetSymbolAddress((void**)&G2, g_G2);
    cudaGetSymbolAddress((void**)&Z,  g_Z);
    cudaGetSymbolAddress((void**)&HA, g_HA);
    cudaGetSymbolAddress((void**)&HB, g_HB);
    cudaGetSymbolAddress((void**)&Wc1, g_Wc1);
    cudaGetSymbolAddress((void**)&Wc2, g_Wc2);
    cudaGetSymbolAddress((void**)&Wc3, g_Wc3);
    cudaGetSymbolAddress((void**)&Wc4, g_Wc4);
    cudaGetSymbolAddress((void**)&G4, g_G4);
    cudaGetSymbolAddress((void**)&Z2, g_Z2);

    // CSR build + weight prep
    k_zero_detect<<<(NN + 255) / 256, 256>>>((const int*)ei);
    k_deg<<<(NE + 255) / 256, 256>>>(ei);
    k_dis<<<(NN + 255) / 256, 256>>>();
    k_scan<<<1, 1024>>>();
    k_scatter<<<(NE + 255) / 256, 256>>>(ei);
    k_prep_all<<<(PWT + 255) / 256, 256>>>(W1, W2, W3, W4);

    dim3 gemmGrid((NN + 127) / 128, 3);
    int spmvBlocks = (NN * 32 + 255) / 256;

    // layer 1: x[N,165] -> HA
    k_gemm_tc<<<gemmGrid, 256>>>(x, 165, Wc1, G0, G1, G2);
    k_spmv128w<<<spmvBlocks, 256>>>(G2, G1, nullptr, Z, 0);
    k_spmv128w<<<spmvBlocks, 256>>>(Z, G0, b1, HA, 1);

    // layer 2: HA -> HB
    k_gemm_tc<<<gemmGrid, 256>>>(HA, 128, Wc2, G0, G1, G2);
    k_spmv128w<<<spmvBlocks, 256>>>(G2, G1, nullptr, Z, 0);
    k_spmv128w<<<spmvBlocks, 256>>>(Z, G0, b2, HB, 1);

    // layer 3: HB -> HA
    k_gemm_tc<<<gemmGrid, 256>>>(HB, 128, Wc3, G0, G1, G2);
    k_spmv128w<<<spmvBlocks, 256>>>(G2, G1, nullptr, Z, 0);
    k_spmv128w<<<spmvBlocks, 256>>>(Z, G0, b3, HA, 1);

    // layer 4: HA -> out[N,2]
    k_gemm_small<<<spmvBlocks, 256>>>(HA, Wc4, G4);
    k_spmv2<<<(NN + 255) / 256, 256>>>(G4, 6, 4, G4, 6, 2, nullptr, Z2, 2, 0);
    k_spmv2<<<(NN + 255) / 256, 256>>>(Z2, 2, 0, G4, 6, 0, b4, out, 2, 0);

    // edge_index tail of the flattened output tuple
    long long tail = (long long)out_size - 2 * NN;
    if (tail == 2 * NE) {
        k_edgecast<<<(2 * NE + 255) / 256, 256>>>(ei, out + 2 * NN);
    } else if (tail == 4 * NE) {
        cudaMemcpyAsync(out + 2 * NN, ei, (size_t)2 * NE * sizeof(long long),
                        cudaMemcpyDeviceToDevice);
    }
}

// round 7
// speedup vs baseline: 2.6950x; 1.0614x over previous
#include <cuda_runtime.h>
#include <stdint.h>

#define NN 100000
#define NE 625000
#define H  128
#define H3 384
#define NSCAN 98   // ceil(NN / 1024)

// ---------------- static device scratch ----------------
__device__ int   g_is64;
__device__ int   g_deg[NN];
__device__ float g_dis[NN];
__device__ int   g_rowptr[NN + 1];
__device__ int   g_cursor[NN];
__device__ int   g_bsum[NSCAN];
__device__ int   g_boff[NSCAN];
__device__ __align__(16) int2  g_edge[NE];     // (src, w bits)
__device__ __align__(16) float g_G0[(size_t)NN * H];
__device__ __align__(16) float g_G1[(size_t)NN * H];
__device__ __align__(16) float g_G2[(size_t)NN * H];
__device__ __align__(16) float g_Z[(size_t)NN * H];
__device__ __align__(16) float g_HA[(size_t)NN * H];
__device__ __align__(16) float g_HB[(size_t)NN * H];
__device__ __align__(16) float g_Wc1[165 * H3];   // 3 segments of [F,128]
__device__ __align__(16) float g_Wc2[128 * H3];
__device__ __align__(16) float g_Wc3[128 * H3];
__device__ __align__(16) float g_Wc4[128 * 6];
__device__ __align__(16) float g_G4[(size_t)NN * 6];
__device__ __align__(16) float g_Z2[(size_t)NN * 2];

__device__ __forceinline__ long long edge_val(const void* ei, long long idx) {
    if (g_is64) return ((const long long*)ei)[idx];
    return (long long)((const int*)ei)[idx];
}

// ---------------- zero deg + dtype detect ----------------
__global__ void k_zero_detect(const int* __restrict__ ei32) {
    int i = blockIdx.x * blockDim.x + threadIdx.x;
    if (i < NN) g_deg[i] = 0;
    if (i == 0) {
        int all_zero = 1;
        for (int t = 0; t < 128; t++)
            if (ei32[2 * t + 1] != 0) { all_zero = 0; break; }
        g_is64 = all_zero;
    }
}

__global__ void k_deg(const void* __restrict__ ei) {
    int e = blockIdx.x * blockDim.x + threadIdx.x;
    if (e < NE) {
        long long d = edge_val(ei, (long long)NE + e);
        if (d >= 0 && d < NN) atomicAdd(&g_deg[(int)d], 1);
    }
}

// ---------------- hierarchical scan ----------------
// phase 1: per-block (1024 elems) exclusive scan + block total; also computes dis
__global__ __launch_bounds__(1024) void k_scan1() {
    __shared__ int warpsum[32];
    int b = blockIdx.x;
    int tid = threadIdx.x, lane = tid & 31, wid = tid >> 5;
    int i = b * 1024 + tid;
    int v = (i < NN) ? g_deg[i] : 0;
    if (i < NN) g_dis[i] = (v > 0) ? rsqrtf((float)v) : 0.0f;
    int inc = v;
#pragma unroll
    for (int off = 1; off < 32; off <<= 1) {
        int t = __shfl_up_sync(0xffffffffu, inc, off);
        if (lane >= off) inc += t;
    }
    if (lane == 31) warpsum[wid] = inc;
    __syncthreads();
    if (wid == 0) {
        int s = warpsum[lane];
        int si = s;
#pragma unroll
        for (int off = 1; off < 32; off <<= 1) {
            int t = __shfl_up_sync(0xffffffffu, si, off);
            if (lane >= off) si += t;
        }
        warpsum[lane] = si - s;   // exclusive warp prefix
    }
    __syncthreads();
    int excl = warpsum[wid] + inc - v;
    if (i < NN) g_rowptr[i] = excl;
    if (tid == 1023) g_bsum[b] = excl + v;   // block total
}

// phase 2: scan 98 block totals (single small block)
__global__ void k_scan2() {
    __shared__ int wsum[4];
    int tid = threadIdx.x, lane = tid & 31, wid = tid >> 5;
    int v = (tid < NSCAN) ? g_bsum[tid] : 0;
    int inc = v;
#pragma unroll
    for (int off = 1; off < 32; off <<= 1) {
        int t = __shfl_up_sync(0xffffffffu, inc, off);
        if (lane >= off) inc += t;
    }
    if (lane == 31) wsum[wid] = inc;
    __syncthreads();
    if (tid == 0) {
        int a = 0;
#pragma unroll
        for (int k = 0; k < 4; k++) { int t = wsum[k]; wsum[k] = a; a += t; }
        g_rowptr[NN] = a;
    }
    __syncthreads();
    int excl = wsum[wid] + inc - v;
    if (tid < NSCAN) g_boff[tid] = excl;
}

// phase 3: apply block offsets, fill cursor
__global__ __launch_bounds__(1024) void k_scan3() {
    int i = blockIdx.x * 1024 + threadIdx.x;
    if (i < NN) {
        int r = g_rowptr[i] + g_boff[blockIdx.x];
        g_rowptr[i] = r;
        g_cursor[i] = r;
    }
}

__global__ void k_scatter(const void* __restrict__ ei) {
    int e = blockIdx.x * blockDim.x + threadIdx.x;
    if (e < NE) {
        long long sl = edge_val(ei, e);
        long long dl = edge_val(ei, (long long)NE + e);
        if (sl < 0 || sl >= NN || dl < 0 || dl >= NN) return;
        int s = (int)sl, d = (int)dl;
        int pos = atomicAdd(&g_cursor[d], 1);
        if (pos >= 0 && pos < NE) {
            float w = -g_dis[s] * g_dis[d];
            g_edge[pos] = make_int2(s, __float_as_int(w));
        }
    }
}

// ---------------- merged combined-weight prep ----------------
__device__ __forceinline__ void prep_one(const float* W, int F, int Hh, float* Wc, int t) {
    int seg = t / (F * Hh);
    int r = t - seg * F * Hh;
    int f = r / Hh;
    int c = r - f * Hh;
    float v;
    if (seg == 0)      v = W[(0 * F + f) * Hh + c] - W[(2 * F + f) * Hh + c];
    else if (seg == 1) v = W[(1 * F + f) * Hh + c];
    else               v = 2.0f * W[(2 * F + f) * Hh + c];
    Wc[(size_t)seg * F * Hh + (size_t)f * Hh + c] = v;
}

#define PW1 (165 * H3)
#define PW2 (PW1 + 128 * H3)
#define PW3 (PW2 + 128 * H3)
#define PWT (PW3 + 128 * 6)

__global__ void k_prep_all(const float* __restrict__ W1, const float* __restrict__ W2,
                           const float* __restrict__ W3, const float* __restrict__ W4) {
    int t = blockIdx.x * blockDim.x + threadIdx.x;
    if (t >= PWT) return;
    if (t < PW1)      prep_one(W1, 165, H, g_Wc1, t);
    else if (t < PW2) prep_one(W2, 128, H, g_Wc2, t - PW1);
    else if (t < PW3) prep_one(W3, 128, H, g_Wc3, t - PW2);
    else {
        int u = t - PW3;           // [128][6] interleaved: (W0-W2, W1, 2W2) x 2 cols
        int f = u / 6;
        int r = u - f * 6;
        int seg = r >> 1;
        int c = r & 1;
        float v;
        if (seg == 0)      v = W4[(0 * 128 + f) * 2 + c] - W4[(2 * 128 + f) * 2 + c];
        else if (seg == 1) v = W4[(1 * 128 + f) * 2 + c];
        else               v = 2.0f * W4[(2 * 128 + f) * 2 + c];
        g_Wc4[f * 6 + r] = v;
    }
}

// ---------------- tf32 helpers ----------------
__device__ __forceinline__ void split_tf32(float x, uint32_t& hi, uint32_t& lo) {
    uint32_t h;
    asm("cvt.rna.tf32.f32 %0, %1;" : "=r"(h) : "f"(x));
    float l = x - __uint_as_float(h);
    uint32_t lw;
    asm("cvt.rna.tf32.f32 %0, %1;" : "=r"(lw) : "f"(l));
    hi = h; lo = lw;
}

__device__ __forceinline__ void mma_tf32(float* c, const uint32_t* a, const uint32_t* b) {
    asm volatile(
        "mma.sync.aligned.m16n8k8.row.col.f32.tf32.tf32.f32 "
        "{%0,%1,%2,%3}, {%4,%5,%6,%7}, {%8,%9}, {%0,%1,%2,%3};"
        : "+f"(c[0]), "+f"(c[1]), "+f"(c[2]), "+f"(c[3])
        : "r"(a[0]), "r"(a[1]), "r"(a[2]), "r"(a[3]), "r"(b[0]), "r"(b[1]));
}

// ---------------- tensor-core GEMM with register-prefetch pipeline ----------------
#define ASTR 20
#define BSTR 136

__global__ __launch_bounds__(256, 2) void k_gemm_tc(
    const float* __restrict__ A, int F,
    const float* __restrict__ B,
    float* __restrict__ C0, float* __restrict__ C1, float* __restrict__ C2)
{
    __shared__ uint32_t As_hi[128 * ASTR];
    __shared__ uint32_t As_lo[128 * ASTR];
    __shared__ uint32_t Bs_hi[16 * BSTR];
    __shared__ uint32_t Bs_lo[16 * BSTR];

    int tid  = threadIdx.x;
    int wid  = tid >> 5, lane = tid & 31;
    int gid  = lane >> 2, tg = lane & 3;
    int wm   = wid & 3;
    int wn   = wid >> 2;
    int bRow = blockIdx.x * 128;

    const float* Bseg = B + (size_t)blockIdx.y * F * H;
    float* Cseg = (blockIdx.y == 0) ? C0 : ((blockIdx.y == 1) ? C1 : C2);

    float acc[2][8][4];
#pragma unroll
    for (int i = 0; i < 2; i++)
#pragma unroll
        for (int j = 0; j < 8; j++)
#pragma unroll
            for (int k = 0; k < 4; k++) acc[i][j][k] = 0.f;

    float  aR[8];
    float4 bR[2];

    // prefetch tile 0
    {
#pragma unroll
        for (int t = 0; t < 8; t++) {
            int l = tid + t * 256;
            int m = l >> 4, k = l & 15;
            int gm = bRow + m, gk = k;
            aR[t] = (gm < NN && gk < F) ? A[(size_t)gm * F + gk] : 0.f;
        }
#pragma unroll
        for (int t = 0; t < 2; t++) {
            int l = tid + t * 256;
            int kr = l >> 5, c4 = l & 31;
            bR[t] = (kr < F) ? *(const float4*)&Bseg[(size_t)kr * H + c4 * 4]
                             : make_float4(0.f, 0.f, 0.f, 0.f);
        }
    }

    for (int k0 = 0; k0 < F; k0 += 16) {
#pragma unroll
        for (int t = 0; t < 8; t++) {
            int l = tid + t * 256;
            int m = l >> 4, k = l & 15;
            uint32_t hi, lo;
            split_tf32(aR[t], hi, lo);
            As_hi[m * ASTR + k] = hi;
            As_lo[m * ASTR + k] = lo;
        }
#pragma unroll
        for (int t = 0; t < 2; t++) {
            int l = tid + t * 256;
            int kr = l >> 5, c4 = l & 31;
            uint32_t hx, lx, hy, ly, hz, lz, hw, lw;
            split_tf32(bR[t].x, hx, lx);
            split_tf32(bR[t].y, hy, ly);
            split_tf32(bR[t].z, hz, lz);
            split_tf32(bR[t].w, hw, lw);
            int o = kr * BSTR + c4 * 4;
            Bs_hi[o] = hx; Bs_hi[o + 1] = hy; Bs_hi[o + 2] = hz; Bs_hi[o + 3] = hw;
            Bs_lo[o] = lx; Bs_lo[o + 1] = ly; Bs_lo[o + 2] = lz; Bs_lo[o + 3] = lw;
        }
        __syncthreads();

        int kn = k0 + 16;
        if (kn < F) {
#pragma unroll
            for (int t = 0; t < 8; t++) {
                int l = tid + t * 256;
                int m = l >> 4, k = l & 15;
                int gm = bRow + m, gk = kn + k;
                aR[t] = (gm < NN && gk < F) ? A[(size_t)gm * F + gk] : 0.f;
            }
#pragma unroll
            for (int t = 0; t < 2; t++) {
                int l = tid + t * 256;
                int kr = l >> 5, c4 = l & 31;
                int gk = kn + kr;
                bR[t] = (gk < F) ? *(const float4*)&Bseg[(size_t)gk * H + c4 * 4]
                                 : make_float4(0.f, 0.f, 0.f, 0.f);
            }
        }

#pragma unroll
        for (int k8 = 0; k8 < 16; k8 += 8) {
            uint32_t ahi[2][4], alo[2][4];
#pragma unroll
            for (int mt = 0; mt < 2; mt++) {
                int m = wm * 32 + mt * 16 + gid;
                ahi[mt][0] = As_hi[m * ASTR + k8 + tg];
                ahi[mt][1] = As_hi[(m + 8) * ASTR + k8 + tg];
                ahi[mt][2] = As_hi[m * ASTR + k8 + tg + 4];
                ahi[mt][3] = As_hi[(m + 8) * ASTR + k8 + tg + 4];
                alo[mt][0] = As_lo[m * ASTR + k8 + tg];
                alo[mt][1] = As_lo[(m + 8) * ASTR + k8 + tg];
                alo[mt][2] = As_lo[m * ASTR + k8 + tg + 4];
                alo[mt][3] = As_lo[(m + 8) * ASTR + k8 + tg + 4];
            }
#pragma unroll
            for (int nt = 0; nt < 8; nt++) {
                int n = wn * 64 + nt * 8 + gid;
                uint32_t bhi[2], blo[2];
                bhi[0] = Bs_hi[(k8 + tg) * BSTR + n];
                bhi[1] = Bs_hi[(k8 + tg + 4) * BSTR + n];
                blo[0] = Bs_lo[(k8 + tg) * BSTR + n];
                blo[1] = Bs_lo[(k8 + tg + 4) * BSTR + n];
#pragma unroll
                for (int mt = 0; mt < 2; mt++) {
                    mma_tf32(acc[mt][nt], ahi[mt], bhi);
                    mma_tf32(acc[mt][nt], ahi[mt], blo);
                    mma_tf32(acc[mt][nt], alo[mt], bhi);
                }
            }
        }
        __syncthreads();
    }

#pragma unroll
    for (int mt = 0; mt < 2; mt++) {
#pragma unroll
        for (int nt = 0; nt < 8; nt++) {
            int gm  = bRow + wm * 32 + mt * 16 + gid;
            int col = wn * 64 + nt * 8 + tg * 2;
            if (gm < NN)
                *(float2*)&Cseg[(size_t)gm * H + col] =
                    make_float2(acc[mt][nt][0], acc[mt][nt][1]);
            if (gm + 8 < NN)
                *(float2*)&Cseg[(size_t)(gm + 8) * H + col] =
                    make_float2(acc[mt][nt][2], acc[mt][nt][3]);
        }
    }
}

// ---------------- small GEMM layer 4 ----------------
__global__ __launch_bounds__(256) void k_gemm_small(
    const float* __restrict__ Hm, const float* __restrict__ Wc, float* __restrict__ G4) {
    __shared__ float Ws[128 * 6];
    for (int i = threadIdx.x; i < 128 * 6; i += blockDim.x) Ws[i] = Wc[i];
    __syncthreads();
    int warp = (blockIdx.x * blockDim.x + threadIdx.x) >> 5;
    int lane = threadIdx.x & 31;
    if (warp >= NN) return;
    int k = lane * 4;
    float4 h = *(const float4*)(Hm + (size_t)warp * 128 + k);
    float acc[6];
#pragma unroll
    for (int c = 0; c < 6; c++)
        acc[c] = h.x * Ws[k * 6 + c] + h.y * Ws[(k + 1) * 6 + c]
               + h.z * Ws[(k + 2) * 6 + c] + h.w * Ws[(k + 3) * 6 + c];
#pragma unroll
    for (int off = 16; off; off >>= 1)
#pragma unroll
        for (int c = 0; c < 6; c++)
            acc[c] += __shfl_down_sync(0xffffffffu, acc[c], off);
    if (lane == 0) {
#pragma unroll
        for (int c = 0; c < 6; c++) G4[(size_t)warp * 6 + c] = acc[c];
    }
}

// ---------------- spmv width-128: warp per node, packed edges, shfl-broadcast ----------
__global__ void k_spmv128w(const float* __restrict__ v,
                           const float* __restrict__ add,
                           const float* __restrict__ bias,
                           float* __restrict__ outp, int doRelu) {
    int idx  = blockIdx.x * blockDim.x + threadIdx.x;
    int warp = idx >> 5;
    int lane = idx & 31;
    if (warp >= NN) return;
    int s = g_rowptr[warp];
    int e = g_rowptr[warp + 1];

    float4 acc = *(const float4*)(add + (size_t)warp * H + lane * 4);
    if (bias) {
        float4 bb = *(const float4*)(bias + lane * 4);
        acc.x += bb.x; acc.y += bb.y; acc.z += bb.z; acc.w += bb.w;
    }

    for (int base = s; base < e; base += 32) {
        int cnt = e - base; if (cnt > 32) cnt = 32;
        int2 ed = make_int2(0, 0);
        if (lane < cnt) ed = g_edge[base + lane];
        for (int j = 0; j < cnt; j++) {
            int   src = __shfl_sync(0xffffffffu, ed.x, j);
            float w   = __int_as_float(__shfl_sync(0xffffffffu, ed.y, j));
            float4 t = *(const float4*)(v + (size_t)src * H + lane * 4);
            acc.x = fmaf(w, t.x, acc.x);
            acc.y = fmaf(w, t.y, acc.y);
            acc.z = fmaf(w, t.z, acc.z);
            acc.w = fmaf(w, t.w, acc.w);
        }
    }
    if (doRelu) {
        acc.x = fminf(fmaxf(acc.x, 0.f), 6.f);
        acc.y = fminf(fmaxf(acc.y, 0.f), 6.f);
        acc.z = fminf(fmaxf(acc.z, 0.f), 6.f);
        acc.w = fminf(fmaxf(acc.w, 0.f), 6.f);
    }
    *(float4*)(outp + (size_t)warp * H + lane * 4) = acc;
}

// ---------------- spmv width-2 (layer 4) ----------------
__global__ void k_spmv2(const float* __restrict__ v, int vs, int vo,
                        const float* __restrict__ add, int as_, int ao,
                        const float* __restrict__ bias,
                        float* __restrict__ outp, int os, int oo) {
    int n = blockIdx.x * blockDim.x + threadIdx.x;
    if (n >= NN) return;
    int s = g_rowptr[n];
    int e = g_rowptr[n + 1];
    float a0 = 0.f, a1 = 0.f;
    for (int i = s; i < e; i++) {
        int2 ed = g_edge[i];
        float w = __int_as_float(ed.y);
        const float* row = v + (size_t)ed.x * vs + vo;
        a0 += w * row[0];
        a1 += w * row[1];
    }
    a0 += add[(size_t)n * as_ + ao];
    a1 += add[(size_t)n * as_ + ao + 1];
    if (bias) { a0 += bias[0]; a1 += bias[1]; }
    outp[(size_t)n * os + oo]     = a0;
    outp[(size_t)n * os + oo + 1] = a1;
}

// ---------------- edge tail ----------------
__global__ void k_edgecast(const void* __restrict__ ei, float* __restrict__ out) {
    int i = blockIdx.x * blockDim.x + threadIdx.x;
    if (i < 2 * NE) out[i] = (float)edge_val(ei, i);
}

// ---------------- launch ----------------
extern "C" void kernel_launch(void* const* d_in, const int* in_sizes, int n_in,
                              void* d_out, int out_size) {
    const float* x  = (const float*)d_in[0];
    const void*  ei = d_in[1];
    const float* W1 = (const float*)d_in[2];
    const float* b1 = (const float*)d_in[3];
    const float* W2 = (const float*)d_in[4];
    const float* b2 = (const float*)d_in[5];
    const float* W3 = (const float*)d_in[6];
    const float* b3 = (const float*)d_in[7];
    const float* W4 = (const float*)d_in[8];
    const float* b4 = (const float*)d_in[9];
    float* out = (float*)d_out;

    float *G0, *G1, *G2, *Z, *HA, *HB, *Wc1, *Wc2, *Wc3, *Wc4, *G4, *Z2;
    cudaGetSymbolAddress((void**)&G0, g_G0);
    cudaGetSymbolAddress((void**)&G1, g_G1);
    cudaGetSymbolAddress((void**)&G2, g_G2);
    cudaGetSymbolAddress((void**)&Z,  g_Z);
    cudaGetSymbolAddress((void**)&HA, g_HA);
    cudaGetSymbolAddress((void**)&HB, g_HB);
    cudaGetSymbolAddress((void**)&Wc1, g_Wc1);
    cudaGetSymbolAddress((void**)&Wc2, g_Wc2);
    cudaGetSymbolAddress((void**)&Wc3, g_Wc3);
    cudaGetSymbolAddress((void**)&Wc4, g_Wc4);
    cudaGetSymbolAddress((void**)&G4, g_G4);
    cudaGetSymbolAddress((void**)&Z2, g_Z2);

    // CSR build + weight prep
    k_zero_detect<<<(NN + 255) / 256, 256>>>((const int*)ei);
    k_deg<<<(NE + 255) / 256, 256>>>(ei);
    k_scan1<<<NSCAN, 1024>>>();
    k_scan2<<<1, 128>>>();
    k_scan3<<<NSCAN, 1024>>>();
    k_scatter<<<(NE + 255) / 256, 256>>>(ei);
    k_prep_all<<<(PWT + 255) / 256, 256>>>(W1, W2, W3, W4);

    dim3 gemmGrid((NN + 127) / 128, 3);
    int spmvBlocks = (NN * 32 + 255) / 256;

    // layer 1: x[N,165] -> HA
    k_gemm_tc<<<gemmGrid, 256>>>(x, 165, Wc1, G0, G1, G2);
    k_spmv128w<<<spmvBlocks, 256>>>(G2, G1, nullptr, Z, 0);
    k_spmv128w<<<spmvBlocks, 256>>>(Z, G0, b1, HA, 1);

    // layer 2: HA -> HB
    k_gemm_tc<<<gemmGrid, 256>>>(HA, 128, Wc2, G0, G1, G2);
    k_spmv128w<<<spmvBlocks, 256>>>(G2, G1, nullptr, Z, 0);
    k_spmv128w<<<spmvBlocks, 256>>>(Z, G0, b2, HB, 1);

    // layer 3: HB -> HA
    k_gemm_tc<<<gemmGrid, 256>>>(HB, 128, Wc3, G0, G1, G2);
    k_spmv128w<<<spmvBlocks, 256>>>(G2, G1, nullptr, Z, 0);
    k_spmv128w<<<spmvBlocks, 256>>>(Z, G0, b3, HA, 1);

    // layer 4: HA -> out[N,2]
    k_gemm_small<<<spmvBlocks, 256>>>(HA, Wc4, G4);
    k_spmv2<<<(NN + 255) / 256, 256>>>(G4, 6, 4, G4, 6, 2, nullptr, Z2, 2, 0);
    k_spmv2<<<(NN + 255) / 256, 256>>>(Z2, 2, 0, G4, 6, 0, b4, out, 2, 0);

    // edge_index tail of the flattened output tuple
    long long tail = (long long)out_size - 2 * NN;
    if (tail == 2 * NE) {
        k_edgecast<<<(2 * NE + 255) / 256, 256>>>(ei, out + 2 * NN);
    } else if (tail == 4 * NE) {
        cudaMemcpyAsync(out + 2 * NN, ei, (size_t)2 * NE * sizeof(long long),
                        cudaMemcpyDeviceToDevice);
    }
}

// round 8
// speedup vs baseline: 3.0937x; 1.1479x over previous
#include <cuda_runtime.h>
#include <cuda_bf16.h>
#include <stdint.h>

#define NN 100000
#define NE 625000
#define H  128
#define H3 384
#define NSCAN 98   // ceil(NN / 1024)

// ---------------- static device scratch ----------------
__device__ int   g_is64;
__device__ int   g_deg[NN];
__device__ float g_dis[NN];
__device__ int   g_rowptr[NN + 1];
__device__ int   g_cursor[NN];
__device__ int   g_bsum[NSCAN];
__device__ int   g_boff[NSCAN];
__device__ __align__(16) int2  g_edge[NE];     // (src, w bits)
__device__ __align__(16) float g_G0[(size_t)NN * H];
__device__ __align__(16) float g_G1[(size_t)NN * H];
__device__ __align__(16) float g_G2[(size_t)NN * H];
__device__ __align__(16) float g_Z[(size_t)NN * H];
__device__ __align__(16) float g_HA[(size_t)NN * H];
__device__ __align__(16) float g_HB[(size_t)NN * H];
__device__ __align__(16) float g_Wc1[165 * H3];   // 3 segments of [F,128]
__device__ __align__(16) float g_Wc2[128 * H3];
__device__ __align__(16) float g_Wc3[128 * H3];
__device__ __align__(16) float g_Wc4[128 * 6];
__device__ __align__(16) float g_G4[(size_t)NN * 6];
__device__ __align__(16) float g_Z2[(size_t)NN * 2];

__device__ __forceinline__ long long edge_val(const void* ei, long long idx) {
    if (g_is64) return ((const long long*)ei)[idx];
    return (long long)((const int*)ei)[idx];
}

// ---------------- zero deg + dtype detect ----------------
__global__ void k_zero_detect(const int* __restrict__ ei32) {
    int i = blockIdx.x * blockDim.x + threadIdx.x;
    if (i < NN) g_deg[i] = 0;
    if (i == 0) {
        int all_zero = 1;
        for (int t = 0; t < 128; t++)
            if (ei32[2 * t + 1] != 0) { all_zero = 0; break; }
        g_is64 = all_zero;
    }
}

__global__ void k_deg(const void* __restrict__ ei) {
    int e = blockIdx.x * blockDim.x + threadIdx.x;
    if (e < NE) {
        long long d = edge_val(ei, (long long)NE + e);
        if (d >= 0 && d < NN) atomicAdd(&g_deg[(int)d], 1);
    }
}

// ---------------- hierarchical scan ----------------
__global__ __launch_bounds__(1024) void k_scan1() {
    __shared__ int warpsum[32];
    int b = blockIdx.x;
    int tid = threadIdx.x, lane = tid & 31, wid = tid >> 5;
    int i = b * 1024 + tid;
    int v = (i < NN) ? g_deg[i] : 0;
    if (i < NN) g_dis[i] = (v > 0) ? rsqrtf((float)v) : 0.0f;
    int inc = v;
#pragma unroll
    for (int off = 1; off < 32; off <<= 1) {
        int t = __shfl_up_sync(0xffffffffu, inc, off);
        if (lane >= off) inc += t;
    }
    if (lane == 31) warpsum[wid] = inc;
    __syncthreads();
    if (wid == 0) {
        int s = warpsum[lane];
        int si = s;
#pragma unroll
        for (int off = 1; off < 32; off <<= 1) {
            int t = __shfl_up_sync(0xffffffffu, si, off);
            if (lane >= off) si += t;
        }
        warpsum[lane] = si - s;
    }
    __syncthreads();
    int excl = warpsum[wid] + inc - v;
    if (i < NN) g_rowptr[i] = excl;
    if (tid == 1023) g_bsum[b] = excl + v;
}

__global__ void k_scan2() {
    __shared__ int wsum[4];
    int tid = threadIdx.x, lane = tid & 31, wid = tid >> 5;
    int v = (tid < NSCAN) ? g_bsum[tid] : 0;
    int inc = v;
#pragma unroll
    for (int off = 1; off < 32; off <<= 1) {
        int t = __shfl_up_sync(0xffffffffu, inc, off);
        if (lane >= off) inc += t;
    }
    if (lane == 31) wsum[wid] = inc;
    __syncthreads();
    if (tid == 0) {
        int a = 0;
#pragma unroll
        for (int k = 0; k < 4; k++) { int t = wsum[k]; wsum[k] = a; a += t; }
        g_rowptr[NN] = a;
    }
    __syncthreads();
    int excl = wsum[wid] + inc - v;
    if (tid < NSCAN) g_boff[tid] = excl;
}

__global__ __launch_bounds__(1024) void k_scan3() {
    int i = blockIdx.x * 1024 + threadIdx.x;
    if (i < NN) {
        int r = g_rowptr[i] + g_boff[blockIdx.x];
        g_rowptr[i] = r;
        g_cursor[i] = r;
    }
}

__global__ void k_scatter(const void* __restrict__ ei) {
    int e = blockIdx.x * blockDim.x + threadIdx.x;
    if (e < NE) {
        long long sl = edge_val(ei, e);
        long long dl = edge_val(ei, (long long)NE + e);
        if (sl < 0 || sl >= NN || dl < 0 || dl >= NN) return;
        int s = (int)sl, d = (int)dl;
        int pos = atomicAdd(&g_cursor[d], 1);
        if (pos >= 0 && pos < NE) {
            float w = -g_dis[s] * g_dis[d];
            g_edge[pos] = make_int2(s, __float_as_int(w));
        }
    }
}

// ---------------- merged combined-weight prep ----------------
__device__ __forceinline__ void prep_one(const float* W, int F, int Hh, float* Wc, int t) {
    int seg = t / (F * Hh);
    int r = t - seg * F * Hh;
    int f = r / Hh;
    int c = r - f * Hh;
    float v;
    if (seg == 0)      v = W[(0 * F + f) * Hh + c] - W[(2 * F + f) * Hh + c];
    else if (seg == 1) v = W[(1 * F + f) * Hh + c];
    else               v = 2.0f * W[(2 * F + f) * Hh + c];
    Wc[(size_t)seg * F * Hh + (size_t)f * Hh + c] = v;
}

#define PW1 (165 * H3)
#define PW2 (PW1 + 128 * H3)
#define PW3 (PW2 + 128 * H3)
#define PWT (PW3 + 128 * 6)

__global__ void k_prep_all(const float* __restrict__ W1, const float* __restrict__ W2,
                           const float* __restrict__ W3, const float* __restrict__ W4) {
    int t = blockIdx.x * blockDim.x + threadIdx.x;
    if (t >= PWT) return;
    if (t < PW1)      prep_one(W1, 165, H, g_Wc1, t);
    else if (t < PW2) prep_one(W2, 128, H, g_Wc2, t - PW1);
    else if (t < PW3) prep_one(W3, 128, H, g_Wc3, t - PW2);
    else {
        int u = t - PW3;
        int f = u / 6;
        int r = u - f * 6;
        int seg = r >> 1;
        int c = r & 1;
        float v;
        if (seg == 0)      v = W4[(0 * 128 + f) * 2 + c] - W4[(2 * 128 + f) * 2 + c];
        else if (seg == 1) v = W4[(1 * 128 + f) * 2 + c];
        else               v = 2.0f * W4[(2 * 128 + f) * 2 + c];
        g_Wc4[f * 6 + r] = v;
    }
}

// ---------------- bf16 split helpers ----------------
// x = hi + mid (each bf16), residual ~2^-16 |x|
__device__ __forceinline__ void split_bf16(float x, uint16_t& hi, uint16_t& mid) {
    __nv_bfloat16 h = __float2bfloat16(x);
    float hf = __bfloat162float(h);
    __nv_bfloat16 m = __float2bfloat16(x - hf);
    hi  = __bfloat16_as_ushort(h);
    mid = __bfloat16_as_ushort(m);
}

__device__ __forceinline__ void mma_bf16(float* c, const uint32_t* a, const uint32_t* b) {
    asm volatile(
        "mma.sync.aligned.m16n8k16.row.col.f32.bf16.bf16.f32 "
        "{%0,%1,%2,%3}, {%4,%5,%6,%7}, {%8,%9}, {%0,%1,%2,%3};"
        : "+f"(c[0]), "+f"(c[1]), "+f"(c[2]), "+f"(c[3])
        : "r"(a[0]), "r"(a[1]), "r"(a[2]), "r"(a[3]), "r"(b[0]), "r"(b[1]));
}

// ---------------- tensor-core GEMM (bf16x2 split): Cseg[NN,128] = A[NN,F] @ Bseg[F,128]
// block tile 128x128, 8 warps 4(M)x2(N), warp tile 32x64, m16n8k16, 3 mmas per K=16
#define ASTRp 12    // uint32 (k-pair) stride for A: 8 pairs + 4 pad -> conflict-free frags
#define BSTRp 136   // uint32 stride for B: 128 + 8 -> conflict-free frags

__global__ __launch_bounds__(256, 2) void k_gemm_tc(
    const float* __restrict__ A, int F,
    const float* __restrict__ B,
    float* __restrict__ C0, float* __restrict__ C1, float* __restrict__ C2)
{
    __shared__ uint32_t As0[128 * ASTRp];   // hi pairs  [m][kp]
    __shared__ uint32_t As1[128 * ASTRp];   // mid pairs
    __shared__ uint32_t Bs0[8 * BSTRp];     // hi pairs  [kp][n]
    __shared__ uint32_t Bs1[8 * BSTRp];     // mid pairs

    int tid  = threadIdx.x;
    int wid  = tid >> 5, lane = tid & 31;
    int gid  = lane >> 2, tg = lane & 3;
    int wm   = wid & 3;
    int wn   = wid >> 2;
    int bRow = blockIdx.x * 128;

    const float* Bseg = B + (size_t)blockIdx.y * F * H;
    float* Cseg = (blockIdx.y == 0) ? C0 : ((blockIdx.y == 1) ? C1 : C2);

    float acc[2][8][4];
#pragma unroll
    for (int i = 0; i < 2; i++)
#pragma unroll
        for (int j = 0; j < 8; j++)
#pragma unroll
            for (int k = 0; k < 4; k++) acc[i][j][k] = 0.f;

    // loader mapping:
    //  A: thread handles row am = tid>>1, k-range ak0 = (tid&1)*8 .. +7 (8 scalars)
    //  B: thread handles k-pair bkp = tid>>5 (0..7), cols bc = (tid&31)*4 .. +3
    int am  = tid >> 1;
    int ak0 = (tid & 1) * 8;
    int bkp = tid >> 5;
    int bc  = (tid & 31) * 4;

    float  aR[8];
    float4 bR0, bR1;

    // prefetch tile 0
    {
        int gm = bRow + am;
#pragma unroll
        for (int j = 0; j < 8; j++) {
            int gk = ak0 + j;
            aR[j] = (gm < NN && gk < F) ? A[(size_t)gm * F + gk] : 0.f;
        }
        int gk0 = 2 * bkp, gk1 = gk0 + 1;
        bR0 = (gk0 < F) ? *(const float4*)&Bseg[(size_t)gk0 * H + bc]
                        : make_float4(0.f, 0.f, 0.f, 0.f);
        bR1 = (gk1 < F) ? *(const float4*)&Bseg[(size_t)gk1 * H + bc]
                        : make_float4(0.f, 0.f, 0.f, 0.f);
    }

    for (int k0 = 0; k0 < F; k0 += 16) {
        // split current registers into packed bf16-pair smem
        {
            uint32_t h[4], m[4];
#pragma unroll
            for (int p = 0; p < 4; p++) {
                uint16_t h0, m0, h1, m1;
                split_bf16(aR[2 * p],     h0, m0);
                split_bf16(aR[2 * p + 1], h1, m1);
                h[p] = (uint32_t)h0 | ((uint32_t)h1 << 16);
                m[p] = (uint32_t)m0 | ((uint32_t)m1 << 16);
            }
            int o = am * ASTRp + (ak0 >> 1);
            *(uint4*)&As0[o] = make_uint4(h[0], h[1], h[2], h[3]);
            *(uint4*)&As1[o] = make_uint4(m[0], m[1], m[2], m[3]);

            const float* lo = &bR0.x;
            const float* hi = &bR1.x;
            uint32_t bh[4], bm[4];
#pragma unroll
            for (int p = 0; p < 4; p++) {
                uint16_t h0, m0, h1, m1;
                split_bf16(lo[p], h0, m0);   // k even
                split_bf16(hi[p], h1, m1);   // k odd
                bh[p] = (uint32_t)h0 | ((uint32_t)h1 << 16);
                bm[p] = (uint32_t)m0 | ((uint32_t)m1 << 16);
            }
            int ob = bkp * BSTRp + bc;
            *(uint4*)&Bs0[ob] = make_uint4(bh[0], bh[1], bh[2], bh[3]);
            *(uint4*)&Bs1[ob] = make_uint4(bm[0], bm[1], bm[2], bm[3]);
        }
        __syncthreads();

        // prefetch next tile (overlaps with MMAs)
        int kn = k0 + 16;
        if (kn < F) {
            int gm = bRow + am;
#pragma unroll
            for (int j = 0; j < 8; j++) {
                int gk = kn + ak0 + j;
                aR[j] = (gm < NN && gk < F) ? A[(size_t)gm * F + gk] : 0.f;
            }
            int gk0 = kn + 2 * bkp, gk1 = gk0 + 1;
            bR0 = (gk0 < F) ? *(const float4*)&Bseg[(size_t)gk0 * H + bc]
                            : make_float4(0.f, 0.f, 0.f, 0.f);
            bR1 = (gk1 < F) ? *(const float4*)&Bseg[(size_t)gk1 * H + bc]
                            : make_float4(0.f, 0.f, 0.f, 0.f);
        }

        // one m16n8k16 step covers the whole 16-deep tile
        {
            uint32_t a0[2][4], a1[2][4];
#pragma unroll
            for (int mt = 0; mt < 2; mt++) {
                int m = wm * 32 + mt * 16 + gid;
                a0[mt][0] = As0[m * ASTRp + tg];
                a0[mt][1] = As0[(m + 8) * ASTRp + tg];
                a0[mt][2] = As0[m * ASTRp + tg + 4];
                a0[mt][3] = As0[(m + 8) * ASTRp + tg + 4];
                a1[mt][0] = As1[m * ASTRp + tg];
                a1[mt][1] = As1[(m + 8) * ASTRp + tg];
                a1[mt][2] = As1[m * ASTRp + tg + 4];
                a1[mt][3] = As1[(m + 8) * ASTRp + tg + 4];
            }
#pragma unroll
            for (int nt = 0; nt < 8; nt++) {
                int n = wn * 64 + nt * 8 + gid;
                uint32_t b0[2], b1[2];
                b0[0] = Bs0[tg * BSTRp + n];
                b0[1] = Bs0[(tg + 4) * BSTRp + n];
                b1[0] = Bs1[tg * BSTRp + n];
                b1[1] = Bs1[(tg + 4) * BSTRp + n];
#pragma unroll
                for (int mt = 0; mt < 2; mt++) {
                    mma_bf16(acc[mt][nt], a0[mt], b0);   // hi*hi
                    mma_bf16(acc[mt][nt], a0[mt], b1);   // hi*mid
                    mma_bf16(acc[mt][nt], a1[mt], b0);   // mid*hi
                }
            }
        }
        __syncthreads();
    }

#pragma unroll
    for (int mt = 0; mt < 2; mt++) {
#pragma unroll
        for (int nt = 0; nt < 8; nt++) {
            int gm  = bRow + wm * 32 + mt * 16 + gid;
            int col = wn * 64 + nt * 8 + tg * 2;
            if (gm < NN)
                *(float2*)&Cseg[(size_t)gm * H + col] =
                    make_float2(acc[mt][nt][0], acc[mt][nt][1]);
            if (gm + 8 < NN)
                *(float2*)&Cseg[(size_t)(gm + 8) * H + col] =
                    make_float2(acc[mt][nt][2], acc[mt][nt][3]);
        }
    }
}

// ---------------- small GEMM layer 4 ----------------
__global__ __launch_bounds__(256) void k_gemm_small(
    const float* __restrict__ Hm, const float* __restrict__ Wc, float* __restrict__ G4) {
    __shared__ float Ws[128 * 6];
    for (int i = threadIdx.x; i < 128 * 6; i += blockDim.x) Ws[i] = Wc[i];
    __syncthreads();
    int warp = (blockIdx.x * blockDim.x + threadIdx.x) >> 5;
    int lane = threadIdx.x & 31;
    if (warp >= NN) return;
    int k = lane * 4;
    float4 h = *(const float4*)(Hm + (size_t)warp * 128 + k);
    float acc[6];
#pragma unroll
    for (int c = 0; c < 6; c++)
        acc[c] = h.x * Ws[k * 6 + c] + h.y * Ws[(k + 1) * 6 + c]
               + h.z * Ws[(k + 2) * 6 + c] + h.w * Ws[(k + 3) * 6 + c];
#pragma unroll
    for (int off = 16; off; off >>= 1)
#pragma unroll
        for (int c = 0; c < 6; c++)
            acc[c] += __shfl_down_sync(0xffffffffu, acc[c], off);
    if (lane == 0) {
#pragma unroll
        for (int c = 0; c < 6; c++) G4[(size_t)warp * 6 + c] = acc[c];
    }
}

// ---------------- spmv width-128: warp per node, packed edges, shfl-broadcast ----------
__global__ void k_spmv128w(const float* __restrict__ v,
                           const float* __restrict__ add,
                           const float* __restrict__ bias,
                           float* __restrict__ outp, int doRelu) {
    int idx  = blockIdx.x * blockDim.x + threadIdx.x;
    int warp = idx >> 5;
    int lane = idx & 31;
    if (warp >= NN) return;
    int s = g_rowptr[warp];
    int e = g_rowptr[warp + 1];

    float4 acc = *(const float4*)(add + (size_t)warp * H + lane * 4);
    if (bias) {
        float4 bb = *(const float4*)(bias + lane * 4);
        acc.x += bb.x; acc.y += bb.y; acc.z += bb.z; acc.w += bb.w;
    }

    for (int base = s; base < e; base += 32) {
        int cnt = e - base; if (cnt > 32) cnt = 32;
        int2 ed = make_int2(0, 0);
        if (lane < cnt) ed = g_edge[base + lane];
        for (int j = 0; j < cnt; j++) {
            int   src = __shfl_sync(0xffffffffu, ed.x, j);
            float w   = __int_as_float(__shfl_sync(0xffffffffu, ed.y, j));
            float4 t = *(const float4*)(v + (size_t)src * H + lane * 4);
            acc.x = fmaf(w, t.x, acc.x);
            acc.y = fmaf(w, t.y, acc.y);
            acc.z = fmaf(w, t.z, acc.z);
            acc.w = fmaf(w, t.w, acc.w);
        }
    }
    if (doRelu) {
        acc.x = fminf(fmaxf(acc.x, 0.f), 6.f);
        acc.y = fminf(fmaxf(acc.y, 0.f), 6.f);
        acc.z = fminf(fmaxf(acc.z, 0.f), 6.f);
        acc.w = fminf(fmaxf(acc.w, 0.f), 6.f);
    }
    *(float4*)(outp + (size_t)warp * H + lane * 4) = acc;
}

// ---------------- spmv width-2 (layer 4) ----------------
__global__ void k_spmv2(const float* __restrict__ v, int vs, int vo,
                        const float* __restrict__ add, int as_, int ao,
                        const float* __restrict__ bias,
                        float* __restrict__ outp, int os, int oo) {
    int n = blockIdx.x * blockDim.x + threadIdx.x;
    if (n >= NN) return;
    int s = g_rowptr[n];
    int e = g_rowptr[n + 1];
    float a0 = 0.f, a1 = 0.f;
    for (int i = s; i < e; i++) {
        int2 ed = g_edge[i];
        float w = __int_as_float(ed.y);
        const float* row = v + (size_t)ed.x * vs + vo;
        a0 += w * row[0];
        a1 += w * row[1];
    }
    a0 += add[(size_t)n * as_ + ao];
    a1 += add[(size_t)n * as_ + ao + 1];
    if (bias) { a0 += bias[0]; a1 += bias[1]; }
    outp[(size_t)n * os + oo]     = a0;
    outp[(size_t)n * os + oo + 1] = a1;
}

// ---------------- edge tail ----------------
__global__ void k_edgecast(const void* __restrict__ ei, float* __restrict__ out) {
    int i = blockIdx.x * blockDim.x + threadIdx.x;
    if (i < 2 * NE) out[i] = (float)edge_val(ei, i);
}

// ---------------- launch ----------------
extern "C" void kernel_launch(void* const* d_in, const int* in_sizes, int n_in,
                              void* d_out, int out_size) {
    const float* x  = (const float*)d_in[0];
    const void*  ei = d_in[1];
    const float* W1 = (const float*)d_in[2];
    const float* b1 = (const float*)d_in[3];
    const float* W2 = (const float*)d_in[4];
    const float* b2 = (const float*)d_in[5];
    const float* W3 = (const float*)d_in[6];
    const float* b3 = (const float*)d_in[7];
    const float* W4 = (const float*)d_in[8];
    const float* b4 = (const float*)d_in[9];
    float* out = (float*)d_out;

    float *G0, *G1, *G2, *Z, *HA, *HB, *Wc1, *Wc2, *Wc3, *Wc4, *G4, *Z2;
    cudaGetSymbolAddress((void**)&G0, g_G0);
    cudaGetSymbolAddress((void**)&G1, g_G1);
    cudaGetSymbolAddress((void**)&G2, g_G2);
    cudaGetSymbolAddress((void**)&Z,  g_Z);
    cudaGetSymbolAddress((void**)&HA, g_HA);
    cudaGetSymbolAddress((void**)&HB, g_HB);
    cudaGetSymbolAddress((void**)&Wc1, g_Wc1);
    cudaGetSymbolAddress((void**)&Wc2, g_Wc2);
    cudaGetSymbolAddress((void**)&Wc3, g_Wc3);
    cudaGetSymbolAddress((void**)&Wc4, g_Wc4);
    cudaGetSymbolAddress((void**)&G4, g_G4);
    cudaGetSymbolAddress((void**)&Z2, g_Z2);

    // CSR build + weight prep
    k_zero_detect<<<(NN + 255) / 256, 256>>>((const int*)ei);
    k_deg<<<(NE + 255) / 256, 256>>>(ei);
    k_scan1<<<NSCAN, 1024>>>();
    k_scan2<<<1, 128>>>();
    k_scan3<<<NSCAN, 1024>>>();
    k_scatter<<<(NE + 255) / 256, 256>>>(ei);
    k_prep_all<<<(PWT + 255) / 256, 256>>>(W1, W2, W3, W4);

    dim3 gemmGrid((NN + 127) / 128, 3);
    int spmvBlocks = (NN * 32 + 255) / 256;

    // layer 1: x[N,165] -> HA
    k_gemm_tc<<<gemmGrid, 256>>>(x, 165, Wc1, G0, G1, G2);
    k_spmv128w<<<spmvBlocks, 256>>>(G2, G1, nullptr, Z, 0);
    k_spmv128w<<<spmvBlocks, 256>>>(Z, G0, b1, HA, 1);

    // layer 2: HA -> HB
    k_gemm_tc<<<gemmGrid, 256>>>(HA, 128, Wc2, G0, G1, G2);
    k_spmv128w<<<spmvBlocks, 256>>>(G2, G1, nullptr, Z, 0);
    k_spmv128w<<<spmvBlocks, 256>>>(Z, G0, b2, HB, 1);

    // layer 3: HB -> HA
    k_gemm_tc<<<gemmGrid, 256>>>(HB, 128, Wc3, G0, G1, G2);
    k_spmv128w<<<spmvBlocks, 256>>>(G2, G1, nullptr, Z, 0);
    k_spmv128w<<<spmvBlocks, 256>>>(Z, G0, b3, HA, 1);

    // layer 4: HA -> out[N,2]
    k_gemm_small<<<spmvBlocks, 256>>>(HA, Wc4, G4);
    k_spmv2<<<(NN + 255) / 256, 256>>>(G4, 6, 4, G4, 6, 2, nullptr, Z2, 2, 0);
    k_spmv2<<<(NN + 255) / 256, 256>>>(Z2, 2, 0, G4, 6, 0, b4, out, 2, 0);

    // edge_index tail of the flattened output tuple
    long long tail = (long long)out_size - 2 * NN;
    if (tail == 2 * NE) {
        k_edgecast<<<(2 * NE + 255) / 256, 256>>>(ei, out + 2 * NN);
    } else if (tail == 4 * NE) {
        cudaMemcpyAsync(out + 2 * NN, ei, (size_t)2 * NE * sizeof(long long),
                        cudaMemcpyDeviceToDevice);
    }
}